// round 3
// baseline (speedup 1.0000x reference)
#include <cuda_runtime.h>
#include <cstdint>

#define NN 100000
#define NE 1600000
#define OUT_DECE (NN)
#define OUT_POS  (NN + NE)
#define OUT_VEL  (NN + NE + NN)

typedef unsigned long long ull;

// ---------------- device-global scratch (no allocations allowed) ----------------
__device__ float4 g_agg[2 * NN];   // [0,NN): sender sums {e0,e1,e2,count}; [NN,2NN): receiver
__device__ float  g_prep[40];      // [0..2]=c_edge, [3]=d_edge, [4..35]=p(node dec), [36]=q
// RK tables packed f32x2: [0..5]=B, [6..11]=CR, [12..35]=CS[s][j] (s*4+j)
__device__ ull g_rk[36];
__device__ ull g_bpk1[16];         // channel-packed biases, ODE layer 1
__device__ ull g_bpk2[16];         // layer 2

// ---------------- packed f32x2 helpers ----------------
__device__ __forceinline__ ull pk2(float lo, float hi) {
    ull r;
    asm("mov.b64 %0, {%1, %2};" : "=l"(r) : "r"(__float_as_uint(lo)), "r"(__float_as_uint(hi)));
    return r;
}
__device__ __forceinline__ void upk2(ull v, float& lo, float& hi) {
    unsigned a, b;
    asm("mov.b64 {%0, %1}, %2;" : "=r"(a), "=r"(b) : "l"(v));
    lo = __uint_as_float(a); hi = __uint_as_float(b);
}
__device__ __forceinline__ ull f2fma(ull a, ull b, ull c) {
    ull d;
    asm("fma.rn.f32x2 %0, %1, %2, %3;" : "=l"(d) : "l"(a), "l"(b), "l"(c));
    return d;
}
__device__ __forceinline__ ull cpkd(float x) {
    unsigned u = __float_as_uint(x);
    return (((ull)u) << 32) | (ull)u;
}

// ---------------- precompute kernel ----------------
__global__ void prep_kernel(const float* __restrict__ eW, const float* __restrict__ eb,
                            const float* __restrict__ decEW, const float* __restrict__ decEb,
                            const float* __restrict__ noW, const float* __restrict__ nob,
                            const float* __restrict__ decNW, const float* __restrict__ decNb,
                            const float* __restrict__ ob1, const float* __restrict__ ob2) {
    int t = threadIdx.x;
    if (t < 3) {
        float s = 0.f;
        for (int c = 0; c < 10; c++) s += eW[t * 10 + c] * decEW[c];
        g_prep[t] = s;
    } else if (t == 3) {
        float s = decEb[0];
        for (int c = 0; c < 10; c++) s += eb[c] * decEW[c];
        g_prep[3] = s;
    } else if (t >= 4 && t < 36) {
        int j = t - 4;
        float s = 0.f;
        for (int c = 0; c < 10; c++) s += noW[j * 10 + c] * decNW[c];
        g_prep[t] = s;
    } else if (t == 36) {
        float s = decNb[0];
        for (int c = 0; c < 10; c++) s += nob[c] * decNW[c];
        g_prep[36] = s;
    } else if (t == 37) {
        const double Hd = 0.1;
        const double B1 = 35.0/384.0, B3 = 500.0/1113.0, B4 = 125.0/192.0,
                     B5 = -2187.0/6784.0, B6 = 11.0/84.0;
        const double A21 = 1.0/5.0;
        const double A31 = 3.0/40.0, A32 = 9.0/40.0;
        const double A41 = 44.0/45.0, A42 = -56.0/15.0, A43 = 32.0/9.0;
        const double A51 = 19372.0/6561.0, A52 = -25360.0/2187.0,
                     A53 = 64448.0/6561.0, A54 = -212.0/729.0;
        const double A61 = 9017.0/3168.0, A62 = -355.0/33.0, A63 = 46732.0/5247.0,
                     A64 = 49.0/176.0, A65 = -5103.0/18656.0;
        // B coefficients
        g_rk[0] = cpkd((float)(Hd * B1));
        g_rk[1] = 0ull;
        g_rk[2] = cpkd((float)(Hd * B3));
        g_rk[3] = cpkd((float)(Hd * B4));
        g_rk[4] = cpkd((float)(Hd * B5));
        g_rk[5] = cpkd((float)(Hd * B6));
        // CR (coefficient of current-stage k)
        g_rk[6 + 0] = cpkd((float)(Hd * (A21 - B1)));
        g_rk[6 + 1] = cpkd((float)(Hd * A32));
        g_rk[6 + 2] = cpkd((float)(Hd * (A43 - B3)));
        g_rk[6 + 3] = cpkd((float)(Hd * (A54 - B4)));
        g_rk[6 + 4] = cpkd((float)(Hd * (A65 - B5)));
        g_rk[6 + 5] = 0ull;
        // CS (coefficients of stored k's)
        for (int i = 12; i < 36; i++) g_rk[i] = 0ull;
        g_rk[12 + 1 * 4 + 0] = cpkd((float)(Hd * (A31 - B1)));
        g_rk[12 + 2 * 4 + 0] = cpkd((float)(Hd * (A41 - B1)));
        g_rk[12 + 2 * 4 + 1] = cpkd((float)(Hd * A42));
        g_rk[12 + 3 * 4 + 0] = cpkd((float)(Hd * (A51 - B1)));
        g_rk[12 + 3 * 4 + 1] = cpkd((float)(Hd * A52));
        g_rk[12 + 3 * 4 + 2] = cpkd((float)(Hd * (A53 - B3)));
        g_rk[12 + 4 * 4 + 0] = cpkd((float)(Hd * (A61 - B1)));
        g_rk[12 + 4 * 4 + 1] = cpkd((float)(Hd * A62));
        g_rk[12 + 4 * 4 + 2] = cpkd((float)(Hd * (A63 - B3)));
        g_rk[12 + 4 * 4 + 3] = cpkd((float)(Hd * (A64 - B4)));
    } else if (t >= 38 && t < 54) {
        int p = t - 38;
        g_bpk1[p] = pk2(ob1[2 * p], ob1[2 * p + 1]);
        g_bpk2[p] = pk2(ob2[2 * p], ob2[2 * p + 1]);
    }
}

__global__ void zero_kernel() {
    int i = blockIdx.x * blockDim.x + threadIdx.x;
    if (i < 2 * NN) g_agg[i] = make_float4(0.f, 0.f, 0.f, 0.f);
}

// ---------------- edge kernel ----------------
__global__ void edge_kernel(const float* __restrict__ edges,
                            const int* __restrict__ senders,
                            const int* __restrict__ receivers,
                            float* __restrict__ out) {
    int e = blockIdx.x * blockDim.x + threadIdx.x;
    if (e >= NE) return;
    float e0 = edges[3 * e + 0];
    float e1 = edges[3 * e + 1];
    float e2 = edges[3 * e + 2];
    int s = senders[e];
    int r = receivers[e];
    float c0 = g_prep[0], c1 = g_prep[1], c2 = g_prep[2], d = g_prep[3];
    out[OUT_DECE + e] = fmaf(e0, c0, fmaf(e1, c1, fmaf(e2, c2, d)));

    float4* ps = &g_agg[s];
    float4* pr = &g_agg[NN + r];
    asm volatile("red.global.add.v4.f32 [%0], {%1, %2, %3, %4};"
                 :: "l"(ps), "f"(e0), "f"(e1), "f"(e2), "f"(1.0f) : "memory");
    asm volatile("red.global.add.v4.f32 [%0], {%1, %2, %3, %4};"
                 :: "l"(pr), "f"(e0), "f"(e1), "f"(e2), "f"(1.0f) : "memory");
}

// ---------------- ODE kernel: 1 node/thread, 2 warps/CTA, 5 CTAs/SM ----------------
// h = bias + v @ W  (v in registers, W broadcast from smem, packed f32x2 accumulate)
__device__ __forceinline__ void mm32(const float* __restrict__ sW, const ull* __restrict__ sB,
                                     const ull* __restrict__ v, ull* __restrict__ h) {
#pragma unroll
    for (int p = 0; p < 16; p++) h[p] = sB[p];
#pragma unroll
    for (int ii = 0; ii < 16; ++ii) {
        float lo, hi;
        upk2(v[ii], lo, hi);
        ull vlo = pk2(lo, lo);
        ull vhi = pk2(hi, hi);
        const ulonglong2* w0 = reinterpret_cast<const ulonglong2*>(sW + ii * 64);
#pragma unroll
        for (int q = 0; q < 8; q++) {
            ulonglong2 a = w0[q];
            h[2 * q]     = f2fma(a.x, vlo, h[2 * q]);
            h[2 * q + 1] = f2fma(a.y, vlo, h[2 * q + 1]);
        }
        const ulonglong2* w1 = reinterpret_cast<const ulonglong2*>(sW + ii * 64 + 32);
#pragma unroll
        for (int q = 0; q < 8; q++) {
            ulonglong2 a = w1[q];
            h[2 * q]     = f2fma(a.x, vhi, h[2 * q]);
            h[2 * q + 1] = f2fma(a.y, vhi, h[2 * q + 1]);
        }
    }
}

__global__ __launch_bounds__(64, 5)
void ode_kernel(const float* __restrict__ nodes, const float* __restrict__ gl,
                const float* __restrict__ encNW, const float* __restrict__ encNb,
                const float* __restrict__ encEW, const float* __restrict__ encEb,
                const float* __restrict__ W1, const float* __restrict__ W2,
                float* __restrict__ out) {
    __shared__ __align__(16) float sW1[1024];
    __shared__ __align__(16) float sW2[1024];
    __shared__ ull sB1[16];
    __shared__ ull sB2[16];
    __shared__ ull sRK[36];
    __shared__ __align__(16) ull sK[2][4][16][32];   // [warp][slot][pair][lane]

    int t = threadIdx.x;                 // 0..63
    int w = t >> 5;
    int l = t & 31;
    for (int i = t; i < 1024; i += 64) { sW1[i] = W1[i]; sW2[i] = W2[i]; }
    if (t < 16) { sB1[t] = g_bpk1[t]; sB2[t] = g_bpk2[t]; }
    if (t >= 16 && t < 52) sRK[t - 16] = g_rk[t - 16];
    __syncthreads();

    int i0 = blockIdx.x * 64 + t;
    bool ok = (i0 < NN);
    int i = ok ? i0 : (NN - 1);

    // ---- encoder ----
    float2 nd = reinterpret_cast<const float2*>(nodes)[i];
    float4 sa = g_agg[i];
    float4 ra = g_agg[NN + i];
    float y[32];
#pragma unroll
    for (int c = 0; c < 10; c++) {
        float wn0 = __ldg(&encNW[c]), wn1 = __ldg(&encNW[10 + c]), bn = __ldg(&encNb[c]);
        y[c] = fmaf(nd.x, wn0, fmaf(nd.y, wn1, bn));
        float we0 = __ldg(&encEW[c]), we1 = __ldg(&encEW[10 + c]);
        float we2 = __ldg(&encEW[20 + c]), web = __ldg(&encEb[c]);
        y[10 + c] = fmaf(sa.x, we0, fmaf(sa.y, we1, fmaf(sa.z, we2, sa.w * web)));
        y[20 + c] = fmaf(ra.x, we0, fmaf(ra.y, we1, fmaf(ra.z, we2, ra.w * web)));
    }
    y[30] = gl[0];
    y[31] = gl[1];

    ull u[16], yn[16], h[16];
#pragma unroll
    for (int p = 0; p < 16; p++) { u[p] = pk2(y[2 * p], y[2 * p + 1]); yn[p] = u[p]; }

    // ---- 10 Dopri5 steps, rebased accumulator scheme ----
#pragma unroll 1
    for (int st = 0; st < 10; ++st) {
#pragma unroll 1
        for (int s = 0; s < 6; ++s) {
            mm32(sW1, sB1, u, h);
#pragma unroll
            for (int p = 0; p < 16; p++) {
                float lo, hi;
                upk2(h[p], lo, hi);
                h[p] = pk2(fmaxf(lo, 0.f), fmaxf(hi, 0.f));
            }
            mm32(sW2, sB2, h, u);       // u now holds k_{s+1}

            // store k slot (s < 4)
            if (s < 4) {
#pragma unroll
                for (int p = 0; p < 16; p++) sK[w][s][p][l] = u[p];
            }
            // yn += B[s] * k
            ull b = sRK[s];
            if (b != 0ull) {
#pragma unroll
                for (int p = 0; p < 16; p++) yn[p] = f2fma(u[p], b, yn[p]);
            }
            // next-stage input
            if (s < 5) {
                ull cr = sRK[6 + s];
#pragma unroll
                for (int p = 0; p < 16; p++) u[p] = f2fma(u[p], cr, yn[p]);
#pragma unroll 1
                for (int j = 0; j < s; ++j) {
                    ull c = sRK[12 + s * 4 + j];
#pragma unroll
                    for (int p = 0; p < 16; p++) u[p] = f2fma(sK[w][j][p][l], c, u[p]);
                }
            } else {
#pragma unroll
                for (int p = 0; p < 16; p++) u[p] = yn[p];
            }
        }
    }

    // ---- fused decode + integrator epilogue ----
    if (ok) {
        float dec = __ldg(&g_prep[36]);
#pragma unroll
        for (int p = 0; p < 16; p++) {
            float pl = __ldg(&g_prep[4 + 2 * p]);
            float ph = __ldg(&g_prep[5 + 2 * p]);
            float lo, hi;
            upk2(u[p], lo, hi);
            dec = fmaf(lo, pl, fmaf(hi, ph, dec));
        }
        out[i] = dec;
        float vel = nd.y + dec;
        out[OUT_VEL + i] = vel;
        out[OUT_POS + i] = nd.x + vel;
    }
}

extern "C" void kernel_launch(void* const* d_in, const int* in_sizes, int n_in,
                              void* d_out, int out_size) {
    const float* nodes     = (const float*)d_in[0];
    const float* edges     = (const float*)d_in[1];
    const int*   senders   = (const int*)d_in[2];
    const int*   receivers = (const int*)d_in[3];
    const float* globals_  = (const float*)d_in[4];
    const float* encNW     = (const float*)d_in[5];
    const float* encNb     = (const float*)d_in[6];
    const float* encEW     = (const float*)d_in[7];
    const float* encEb     = (const float*)d_in[8];
    const float* odeW1     = (const float*)d_in[9];
    const float* odeb1     = (const float*)d_in[10];
    const float* odeW2     = (const float*)d_in[11];
    const float* odeb2     = (const float*)d_in[12];
    const float* noW       = (const float*)d_in[13];
    const float* nob       = (const float*)d_in[14];
    const float* decNW     = (const float*)d_in[15];
    const float* decNb     = (const float*)d_in[16];
    const float* decEW     = (const float*)d_in[17];
    const float* decEb     = (const float*)d_in[18];
    float* out = (float*)d_out;

    prep_kernel<<<1, 64>>>(encEW, encEb, decEW, decEb, noW, nob, decNW, decNb, odeb1, odeb2);
    zero_kernel<<<(2 * NN + 255) / 256, 256>>>();
    edge_kernel<<<(NE + 255) / 256, 256>>>(edges, senders, receivers, out);
    int nblk = (NN + 63) / 64;
    ode_kernel<<<nblk, 64>>>(nodes, globals_, encNW, encNb, encEW, encEb,
                             odeW1, odeW2, out);
}

// round 4
// speedup vs baseline: 1.0060x; 1.0060x over previous
#include <cuda_runtime.h>
#include <cstdint>

#define NN 100000
#define NE 1600000
#define OUT_DECE (NN)
#define OUT_POS  (NN + NE)
#define OUT_VEL  (NN + NE + NN)

typedef unsigned long long ull;

// ---------------- device-global scratch (no allocations allowed) ----------------
__device__ float4 g_agg[2 * NN];   // [0,NN): sender sums {e0,e1,e2,count}; [NN,2NN): receiver
__device__ float  g_prep[40];      // [0..2]=c_edge, [3]=d_edge, [4..35]=p(node dec), [36]=q
// RK tables packed f32x2: [0..5]=B, [6..11]=CR, [12..35]=CS[s][j] (s*4+j)
__device__ ull g_rk[36];
__device__ ull g_bpk1[16];         // channel-packed biases, ODE layer 1
__device__ ull g_bpk2[16];         // layer 2

// ---------------- packed f32x2 helpers ----------------
__device__ __forceinline__ ull pk2(float lo, float hi) {
    ull r;
    asm("mov.b64 %0, {%1, %2};" : "=l"(r) : "r"(__float_as_uint(lo)), "r"(__float_as_uint(hi)));
    return r;
}
__device__ __forceinline__ void upk2(ull v, float& lo, float& hi) {
    unsigned a, b;
    asm("mov.b64 {%0, %1}, %2;" : "=r"(a), "=r"(b) : "l"(v));
    lo = __uint_as_float(a); hi = __uint_as_float(b);
}
__device__ __forceinline__ ull f2fma(ull a, ull b, ull c) {
    ull d;
    asm("fma.rn.f32x2 %0, %1, %2, %3;" : "=l"(d) : "l"(a), "l"(b), "l"(c));
    return d;
}
__device__ __forceinline__ ull cpkd(float x) {
    unsigned u = __float_as_uint(x);
    return (((ull)u) << 32) | (ull)u;
}

// ---------------- precompute kernel ----------------
__global__ void prep_kernel(const float* __restrict__ eW, const float* __restrict__ eb,
                            const float* __restrict__ decEW, const float* __restrict__ decEb,
                            const float* __restrict__ noW, const float* __restrict__ nob,
                            const float* __restrict__ decNW, const float* __restrict__ decNb,
                            const float* __restrict__ ob1, const float* __restrict__ ob2) {
    int t = threadIdx.x;
    if (t < 3) {
        float s = 0.f;
        for (int c = 0; c < 10; c++) s += eW[t * 10 + c] * decEW[c];
        g_prep[t] = s;
    } else if (t == 3) {
        float s = decEb[0];
        for (int c = 0; c < 10; c++) s += eb[c] * decEW[c];
        g_prep[3] = s;
    } else if (t >= 4 && t < 36) {
        int j = t - 4;
        float s = 0.f;
        for (int c = 0; c < 10; c++) s += noW[j * 10 + c] * decNW[c];
        g_prep[t] = s;
    } else if (t == 36) {
        float s = decNb[0];
        for (int c = 0; c < 10; c++) s += nob[c] * decNW[c];
        g_prep[36] = s;
    } else if (t == 37) {
        const double Hd = 0.1;
        const double B1 = 35.0/384.0, B3 = 500.0/1113.0, B4 = 125.0/192.0,
                     B5 = -2187.0/6784.0, B6 = 11.0/84.0;
        const double A21 = 1.0/5.0;
        const double A31 = 3.0/40.0, A32 = 9.0/40.0;
        const double A41 = 44.0/45.0, A42 = -56.0/15.0, A43 = 32.0/9.0;
        const double A51 = 19372.0/6561.0, A52 = -25360.0/2187.0,
                     A53 = 64448.0/6561.0, A54 = -212.0/729.0;
        const double A61 = 9017.0/3168.0, A62 = -355.0/33.0, A63 = 46732.0/5247.0,
                     A64 = 49.0/176.0, A65 = -5103.0/18656.0;
        // B coefficients
        g_rk[0] = cpkd((float)(Hd * B1));
        g_rk[1] = 0ull;
        g_rk[2] = cpkd((float)(Hd * B3));
        g_rk[3] = cpkd((float)(Hd * B4));
        g_rk[4] = cpkd((float)(Hd * B5));
        g_rk[5] = cpkd((float)(Hd * B6));
        // CR (coefficient of current-stage k)
        g_rk[6 + 0] = cpkd((float)(Hd * (A21 - B1)));
        g_rk[6 + 1] = cpkd((float)(Hd * A32));
        g_rk[6 + 2] = cpkd((float)(Hd * (A43 - B3)));
        g_rk[6 + 3] = cpkd((float)(Hd * (A54 - B4)));
        g_rk[6 + 4] = cpkd((float)(Hd * (A65 - B5)));
        g_rk[6 + 5] = 0ull;
        // CS (coefficients of stored k's)
        for (int i = 12; i < 36; i++) g_rk[i] = 0ull;
        g_rk[12 + 1 * 4 + 0] = cpkd((float)(Hd * (A31 - B1)));
        g_rk[12 + 2 * 4 + 0] = cpkd((float)(Hd * (A41 - B1)));
        g_rk[12 + 2 * 4 + 1] = cpkd((float)(Hd * A42));
        g_rk[12 + 3 * 4 + 0] = cpkd((float)(Hd * (A51 - B1)));
        g_rk[12 + 3 * 4 + 1] = cpkd((float)(Hd * A52));
        g_rk[12 + 3 * 4 + 2] = cpkd((float)(Hd * (A53 - B3)));
        g_rk[12 + 4 * 4 + 0] = cpkd((float)(Hd * (A61 - B1)));
        g_rk[12 + 4 * 4 + 1] = cpkd((float)(Hd * A62));
        g_rk[12 + 4 * 4 + 2] = cpkd((float)(Hd * (A63 - B3)));
        g_rk[12 + 4 * 4 + 3] = cpkd((float)(Hd * (A64 - B4)));
    } else if (t >= 38 && t < 54) {
        int p = t - 38;
        g_bpk1[p] = pk2(ob1[2 * p], ob1[2 * p + 1]);
        g_bpk2[p] = pk2(ob2[2 * p], ob2[2 * p + 1]);
    }
}

__global__ void zero_kernel() {
    int i = blockIdx.x * blockDim.x + threadIdx.x;
    if (i < 2 * NN) g_agg[i] = make_float4(0.f, 0.f, 0.f, 0.f);
}

// ---------------- edge kernel ----------------
__global__ void edge_kernel(const float* __restrict__ edges,
                            const int* __restrict__ senders,
                            const int* __restrict__ receivers,
                            float* __restrict__ out) {
    int e = blockIdx.x * blockDim.x + threadIdx.x;
    if (e >= NE) return;
    float e0 = edges[3 * e + 0];
    float e1 = edges[3 * e + 1];
    float e2 = edges[3 * e + 2];
    int s = senders[e];
    int r = receivers[e];
    float c0 = g_prep[0], c1 = g_prep[1], c2 = g_prep[2], d = g_prep[3];
    out[OUT_DECE + e] = fmaf(e0, c0, fmaf(e1, c1, fmaf(e2, c2, d)));

    float4* ps = &g_agg[s];
    float4* pr = &g_agg[NN + r];
    asm volatile("red.global.add.v4.f32 [%0], {%1, %2, %3, %4};"
                 :: "l"(ps), "f"(e0), "f"(e1), "f"(e2), "f"(1.0f) : "memory");
    asm volatile("red.global.add.v4.f32 [%0], {%1, %2, %3, %4};"
                 :: "l"(pr), "f"(e0), "f"(e1), "f"(e2), "f"(1.0f) : "memory");
}

// ---------------- ODE kernel: 1 node/thread, 2 warps/CTA, no reg cap ----------------
// h = bias + v @ W  (v in registers, W broadcast from smem, packed f32x2 accumulate)
__device__ __forceinline__ void mm32(const float* __restrict__ sW, const ull* __restrict__ sB,
                                     const ull* __restrict__ v, ull* __restrict__ h) {
#pragma unroll
    for (int p = 0; p < 16; p++) h[p] = sB[p];
#pragma unroll
    for (int ii = 0; ii < 16; ++ii) {
        float lo, hi;
        upk2(v[ii], lo, hi);
        ull vlo = pk2(lo, lo);
        ull vhi = pk2(hi, hi);
        const ulonglong2* w0 = reinterpret_cast<const ulonglong2*>(sW + ii * 64);
#pragma unroll
        for (int q = 0; q < 8; q++) {
            ulonglong2 a = w0[q];
            h[2 * q]     = f2fma(a.x, vlo, h[2 * q]);
            h[2 * q + 1] = f2fma(a.y, vlo, h[2 * q + 1]);
        }
        const ulonglong2* w1 = reinterpret_cast<const ulonglong2*>(sW + ii * 64 + 32);
#pragma unroll
        for (int q = 0; q < 8; q++) {
            ulonglong2 a = w1[q];
            h[2 * q]     = f2fma(a.x, vhi, h[2 * q]);
            h[2 * q + 1] = f2fma(a.y, vhi, h[2 * q + 1]);
        }
    }
}

__global__ __launch_bounds__(64)
void ode_kernel(const float* __restrict__ nodes, const float* __restrict__ gl,
                const float* __restrict__ encNW, const float* __restrict__ encNb,
                const float* __restrict__ encEW, const float* __restrict__ encEb,
                const float* __restrict__ W1, const float* __restrict__ W2,
                float* __restrict__ out) {
    __shared__ __align__(16) float sW1[1024];
    __shared__ __align__(16) float sW2[1024];
    __shared__ ull sB1[16];
    __shared__ ull sB2[16];
    __shared__ ull sRK[36];
    __shared__ __align__(16) ull sK[2][4][16][32];   // [warp][slot][pair][lane]

    int t = threadIdx.x;                 // 0..63
    int w = t >> 5;
    int l = t & 31;
    for (int i = t; i < 1024; i += 64) { sW1[i] = W1[i]; sW2[i] = W2[i]; }
    if (t < 16) { sB1[t] = g_bpk1[t]; sB2[t] = g_bpk2[t]; }
    if (t >= 16 && t < 52) sRK[t - 16] = g_rk[t - 16];
    __syncthreads();

    int i0 = blockIdx.x * 64 + t;
    bool ok = (i0 < NN);
    int i = ok ? i0 : (NN - 1);

    // ---- encoder ----
    float2 nd = reinterpret_cast<const float2*>(nodes)[i];
    float4 sa = g_agg[i];
    float4 ra = g_agg[NN + i];
    float y[32];
#pragma unroll
    for (int c = 0; c < 10; c++) {
        float wn0 = __ldg(&encNW[c]), wn1 = __ldg(&encNW[10 + c]), bn = __ldg(&encNb[c]);
        y[c] = fmaf(nd.x, wn0, fmaf(nd.y, wn1, bn));
        float we0 = __ldg(&encEW[c]), we1 = __ldg(&encEW[10 + c]);
        float we2 = __ldg(&encEW[20 + c]), web = __ldg(&encEb[c]);
        y[10 + c] = fmaf(sa.x, we0, fmaf(sa.y, we1, fmaf(sa.z, we2, sa.w * web)));
        y[20 + c] = fmaf(ra.x, we0, fmaf(ra.y, we1, fmaf(ra.z, we2, ra.w * web)));
    }
    y[30] = gl[0];
    y[31] = gl[1];

    ull u[16], yn[16], h[16];
#pragma unroll
    for (int p = 0; p < 16; p++) { u[p] = pk2(y[2 * p], y[2 * p + 1]); yn[p] = u[p]; }

    // ---- 10 Dopri5 steps, rebased accumulator scheme ----
#pragma unroll 1
    for (int st = 0; st < 10; ++st) {
#pragma unroll 1
        for (int s = 0; s < 6; ++s) {
            mm32(sW1, sB1, u, h);
#pragma unroll
            for (int p = 0; p < 16; p++) {
                float lo, hi;
                upk2(h[p], lo, hi);
                h[p] = pk2(fmaxf(lo, 0.f), fmaxf(hi, 0.f));
            }
            mm32(sW2, sB2, h, u);       // u now holds k_{s+1}

            // store k slot (s < 4)
            if (s < 4) {
#pragma unroll
                for (int p = 0; p < 16; p++) sK[w][s][p][l] = u[p];
            }
            // yn += B[s] * k   (B[1] is packed zero -> exact no-op contribution)
            ull b = sRK[s];
#pragma unroll
            for (int p = 0; p < 16; p++) yn[p] = f2fma(u[p], b, yn[p]);

            // next-stage input
            if (s < 5) {
                ull cr = sRK[6 + s];
#pragma unroll
                for (int p = 0; p < 16; p++) u[p] = f2fma(u[p], cr, yn[p]);
#pragma unroll 1
                for (int j = 0; j < s; ++j) {
                    ull c = sRK[12 + s * 4 + j];
#pragma unroll
                    for (int p = 0; p < 16; p++) u[p] = f2fma(sK[w][j][p][l], c, u[p]);
                }
            } else {
#pragma unroll
                for (int p = 0; p < 16; p++) u[p] = yn[p];
            }
        }
    }

    // ---- fused decode + integrator epilogue ----
    if (ok) {
        float dec = __ldg(&g_prep[36]);
#pragma unroll
        for (int p = 0; p < 16; p++) {
            float pl = __ldg(&g_prep[4 + 2 * p]);
            float ph = __ldg(&g_prep[5 + 2 * p]);
            float lo, hi;
            upk2(u[p], lo, hi);
            dec = fmaf(lo, pl, fmaf(hi, ph, dec));
        }
        out[i] = dec;
        float vel = nd.y + dec;
        out[OUT_VEL + i] = vel;
        out[OUT_POS + i] = nd.x + vel;
    }
}

extern "C" void kernel_launch(void* const* d_in, const int* in_sizes, int n_in,
                              void* d_out, int out_size) {
    const float* nodes     = (const float*)d_in[0];
    const float* edges     = (const float*)d_in[1];
    const int*   senders   = (const int*)d_in[2];
    const int*   receivers = (const int*)d_in[3];
    const float* globals_  = (const float*)d_in[4];
    const float* encNW     = (const float*)d_in[5];
    const float* encNb     = (const float*)d_in[6];
    const float* encEW     = (const float*)d_in[7];
    const float* encEb     = (const float*)d_in[8];
    const float* odeW1     = (const float*)d_in[9];
    const float* odeb1     = (const float*)d_in[10];
    const float* odeW2     = (const float*)d_in[11];
    const float* odeb2     = (const float*)d_in[12];
    const float* noW       = (const float*)d_in[13];
    const float* nob       = (const float*)d_in[14];
    const float* decNW     = (const float*)d_in[15];
    const float* decNb     = (const float*)d_in[16];
    const float* decEW     = (const float*)d_in[17];
    const float* decEb     = (const float*)d_in[18];
    float* out = (float*)d_out;

    prep_kernel<<<1, 64>>>(encEW, encEb, decEW, decEb, noW, nob, decNW, decNb, odeb1, odeb2);
    zero_kernel<<<(2 * NN + 255) / 256, 256>>>();
    edge_kernel<<<(NE + 255) / 256, 256>>>(edges, senders, receivers, out);
    int nblk = (NN + 63) / 64;
    ode_kernel<<<nblk, 64>>>(nodes, globals_, encNW, encNb, encEW, encEb,
                             odeW1, odeW2, out);
}

// round 5
// speedup vs baseline: 10.8777x; 10.8131x over previous
#include <cuda_runtime.h>
#include <cstdint>

#define NN 100000
#define NE 1600000
#define OUT_DECE (NN)
#define OUT_POS  (NN + NE)
#define OUT_VEL  (NN + NE + NN)

typedef unsigned long long ull;

// ---------------- device-global scratch (no allocations allowed) ----------------
__device__ float4 g_agg[2 * NN];   // [0,NN): sender sums {e0,e1,e2,count}; [NN,2NN): receiver
__device__ float  g_prep[40];      // [0..2]=c_edge, [3]=d_edge, [4..35]=p(node dec), [36]=q

// ---------------- RK coefficients (compile-time, H=0.1 absorbed, rebased on yn) ----
#define C_B1   ((float)(0.1 * (35.0/384.0)))
#define C_B3   ((float)(0.1 * (500.0/1113.0)))
#define C_B4   ((float)(0.1 * (125.0/192.0)))
#define C_B5   ((float)(0.1 * (-2187.0/6784.0)))
#define C_B6   ((float)(0.1 * (11.0/84.0)))
#define C_R1   ((float)(0.1 * (1.0/5.0 - 35.0/384.0)))            // u2: coeff of k1
#define C_S31  ((float)(0.1 * (3.0/40.0 - 35.0/384.0)))           // u3: k1
#define C_R2   ((float)(0.1 * (9.0/40.0)))                        // u3: k2
#define C_S41  ((float)(0.1 * (44.0/45.0 - 35.0/384.0)))          // u4: k1
#define C_S42  ((float)(0.1 * (-56.0/15.0)))                      // u4: k2
#define C_R3   ((float)(0.1 * (32.0/9.0 - 500.0/1113.0)))         // u4: k3
#define C_S51  ((float)(0.1 * (19372.0/6561.0 - 35.0/384.0)))     // u5: k1
#define C_S52  ((float)(0.1 * (-25360.0/2187.0)))                 // u5: k2
#define C_S53  ((float)(0.1 * (64448.0/6561.0 - 500.0/1113.0)))   // u5: k3
#define C_R4   ((float)(0.1 * (-212.0/729.0 - 125.0/192.0)))      // u5: k4
#define C_S61  ((float)(0.1 * (9017.0/3168.0 - 35.0/384.0)))      // u6: k1
#define C_S62  ((float)(0.1 * (-355.0/33.0)))                     // u6: k2
#define C_S63  ((float)(0.1 * (46732.0/5247.0 - 500.0/1113.0)))   // u6: k3
#define C_S64  ((float)(0.1 * (49.0/176.0 - 125.0/192.0)))        // u6: k4
#define C_R5   ((float)(0.1 * (-5103.0/18656.0 + 2187.0/6784.0))) // u6: k5

// ---------------- packed f32x2 helpers ----------------
__device__ __forceinline__ ull pk2(float lo, float hi) {
    ull r;
    asm("mov.b64 %0, {%1, %2};" : "=l"(r) : "r"(__float_as_uint(lo)), "r"(__float_as_uint(hi)));
    return r;
}
__device__ __forceinline__ void upk2(ull v, float& lo, float& hi) {
    unsigned a, b;
    asm("mov.b64 {%0, %1}, %2;" : "=r"(a), "=r"(b) : "l"(v));
    lo = __uint_as_float(a); hi = __uint_as_float(b);
}
__device__ __forceinline__ ull f2fma(ull a, ull b, ull c) {
    ull d;
    asm("fma.rn.f32x2 %0, %1, %2, %3;" : "=l"(d) : "l"(a), "l"(b), "l"(c));
    return d;
}
__device__ __forceinline__ ull cpk(float x) {
    unsigned u = __float_as_uint(x);
    return (((ull)u) << 32) | (ull)u;
}

// ---------------- precompute kernel ----------------
__global__ void prep_kernel(const float* __restrict__ eW, const float* __restrict__ eb,
                            const float* __restrict__ decEW, const float* __restrict__ decEb,
                            const float* __restrict__ noW, const float* __restrict__ nob,
                            const float* __restrict__ decNW, const float* __restrict__ decNb) {
    int t = threadIdx.x;
    if (t < 3) {
        float s = 0.f;
        for (int c = 0; c < 10; c++) s += eW[t * 10 + c] * decEW[c];
        g_prep[t] = s;
    } else if (t == 3) {
        float s = decEb[0];
        for (int c = 0; c < 10; c++) s += eb[c] * decEW[c];
        g_prep[3] = s;
    } else if (t >= 4 && t < 36) {
        int j = t - 4;
        float s = 0.f;
        for (int c = 0; c < 10; c++) s += noW[j * 10 + c] * decNW[c];
        g_prep[t] = s;
    } else if (t == 36) {
        float s = decNb[0];
        for (int c = 0; c < 10; c++) s += nob[c] * decNW[c];
        g_prep[36] = s;
    }
}

__global__ void zero_kernel() {
    int i = blockIdx.x * blockDim.x + threadIdx.x;
    if (i < 2 * NN) g_agg[i] = make_float4(0.f, 0.f, 0.f, 0.f);
}

// ---------------- edge kernel ----------------
__global__ void edge_kernel(const float* __restrict__ edges,
                            const int* __restrict__ senders,
                            const int* __restrict__ receivers,
                            float* __restrict__ out) {
    int e = blockIdx.x * blockDim.x + threadIdx.x;
    if (e >= NE) return;
    float e0 = edges[3 * e + 0];
    float e1 = edges[3 * e + 1];
    float e2 = edges[3 * e + 2];
    int s = senders[e];
    int r = receivers[e];
    float c0 = g_prep[0], c1 = g_prep[1], c2 = g_prep[2], d = g_prep[3];
    out[OUT_DECE + e] = fmaf(e0, c0, fmaf(e1, c1, fmaf(e2, c2, d)));

    float4* ps = &g_agg[s];
    float4* pr = &g_agg[NN + r];
    asm volatile("red.global.add.v4.f32 [%0], {%1, %2, %3, %4};"
                 :: "l"(ps), "f"(e0), "f"(e1), "f"(e2), "f"(1.0f) : "memory");
    asm volatile("red.global.add.v4.f32 [%0], {%1, %2, %3, %4};"
                 :: "l"(pr), "f"(e0), "f"(e1), "f"(e2), "f"(1.0f) : "memory");
}

// ---------------- ODE kernel ----------------
// f(A): h = relu(A@W1+b1) written back to A's smem column; k = A@W2+b2 left in h regs.
// Input vector lives in per-thread SMEM column (stride 64 ull). h[] is the ONLY
// register array, compile-time indexed, live only within one matmul.
__device__ __forceinline__ void mm_s(const float* __restrict__ sW,
                                     const ull* __restrict__ sB,
                                     const ull* __restrict__ vcol, ull h[16]) {
#pragma unroll
    for (int p = 0; p < 16; p++) h[p] = sB[p];
#pragma unroll 1
    for (int ii = 0; ii < 16; ++ii) {
        float lo, hi;
        upk2(vcol[ii * 64], lo, hi);
        ull vlo = pk2(lo, lo);
        ull vhi = pk2(hi, hi);
        const ulonglong2* w0 = reinterpret_cast<const ulonglong2*>(sW + ii * 64);
#pragma unroll
        for (int q = 0; q < 8; q++) {
            ulonglong2 a = w0[q];
            h[2 * q]     = f2fma(a.x, vlo, h[2 * q]);
            h[2 * q + 1] = f2fma(a.y, vlo, h[2 * q + 1]);
        }
        const ulonglong2* w1 = reinterpret_cast<const ulonglong2*>(sW + ii * 64 + 32);
#pragma unroll
        for (int q = 0; q < 8; q++) {
            ulonglong2 a = w1[q];
            h[2 * q]     = f2fma(a.x, vhi, h[2 * q]);
            h[2 * q + 1] = f2fma(a.y, vhi, h[2 * q + 1]);
        }
    }
}

__global__ __launch_bounds__(64)
void ode_kernel(const float* __restrict__ nodes, const float* __restrict__ gl,
                const float* __restrict__ encNW, const float* __restrict__ encNb,
                const float* __restrict__ encEW, const float* __restrict__ encEb,
                const float* __restrict__ W1, const float* __restrict__ b1,
                const float* __restrict__ W2, const float* __restrict__ b2,
                float* __restrict__ out) {
    __shared__ __align__(16) float sW1[1024];
    __shared__ __align__(16) float sW2[1024];
    __shared__ ull sB1[16];
    __shared__ ull sB2[16];
    __shared__ __align__(16) ull sA[16 * 64];    // stage input vector
    __shared__ __align__(16) ull sYn[16 * 64];   // running y accumulator
    __shared__ __align__(16) ull sK1[16 * 64];   // k1
    __shared__ __align__(16) ull sK2[16 * 64];   // k2

    int t = threadIdx.x;   // 0..63
    for (int i = t; i < 1024; i += 64) { sW1[i] = W1[i]; sW2[i] = W2[i]; }
    if (t < 16) {
        sB1[t] = pk2(b1[2 * t], b1[2 * t + 1]);
        sB2[t] = pk2(b2[2 * t], b2[2 * t + 1]);
    }
    __syncthreads();

    int i0 = blockIdx.x * 64 + t;
    bool ok = (i0 < NN);
    int i = ok ? i0 : (NN - 1);

    ull* a  = &sA[t];
    ull* yn = &sYn[t];
    ull* k1 = &sK1[t];
    ull* k2 = &sK2[t];

    // ---- encoder: y = [h_n(10) | sent(10) | recv(10) | g(2)] ----
    float2 nd = reinterpret_cast<const float2*>(nodes)[i];
    float4 sa = g_agg[i];
    float4 ra = g_agg[NN + i];
    {
        float y[32];
#pragma unroll
        for (int c = 0; c < 10; c++) {
            float wn0 = __ldg(&encNW[c]), wn1 = __ldg(&encNW[10 + c]), bn = __ldg(&encNb[c]);
            y[c] = fmaf(nd.x, wn0, fmaf(nd.y, wn1, bn));
            float we0 = __ldg(&encEW[c]), we1 = __ldg(&encEW[10 + c]);
            float we2 = __ldg(&encEW[20 + c]), web = __ldg(&encEb[c]);
            y[10 + c] = fmaf(sa.x, we0, fmaf(sa.y, we1, fmaf(sa.z, we2, sa.w * web)));
            y[20 + c] = fmaf(ra.x, we0, fmaf(ra.y, we1, fmaf(ra.z, we2, ra.w * web)));
        }
        y[30] = gl[0];
        y[31] = gl[1];
#pragma unroll
        for (int p = 0; p < 16; p++) {
            ull v = pk2(y[2 * p], y[2 * p + 1]);
            a[p * 64] = v;
            yn[p * 64] = v;
        }
    }

    ull h[16];        // matmul accumulator (only register array; compile-time indexed)
    ull k3r[16], k4r[16];  // short-lived register copies of k3, k4

    // f: h = A@W1+b1; relu -> back into A column; h = A@W2+b2 (k result in h)
#define FEVAL()                                                         \
    do {                                                                \
        mm_s(sW1, sB1, a, h);                                           \
        _Pragma("unroll")                                               \
        for (int p = 0; p < 16; p++) {                                  \
            float lo, hi;                                               \
            upk2(h[p], lo, hi);                                         \
            a[p * 64] = pk2(fmaxf(lo, 0.f), fmaxf(hi, 0.f));            \
        }                                                               \
        mm_s(sW2, sB2, a, h);                                           \
    } while (0)

#pragma unroll 1
    for (int st = 0; st < 10; ++st) {
        // ---- stage 1 ----
        FEVAL();
        {
            const ull cb = cpk(C_B1), cr = cpk(C_R1);
#pragma unroll
            for (int p = 0; p < 16; p++) {
                k1[p * 64] = h[p];
                ull yv = f2fma(h[p], cb, yn[p * 64]);
                yn[p * 64] = yv;
                a[p * 64] = f2fma(h[p], cr, yv);
            }
        }
        // ---- stage 2 ----
        FEVAL();
        {
            const ull c1 = cpk(C_S31), cr = cpk(C_R2);
#pragma unroll
            for (int p = 0; p < 16; p++) {
                k2[p * 64] = h[p];
                ull tv = f2fma(k1[p * 64], c1, yn[p * 64]);
                a[p * 64] = f2fma(h[p], cr, tv);
            }
        }
        // ---- stage 3 ----
        FEVAL();
        {
            const ull cb = cpk(C_B3), c1 = cpk(C_S41), c2 = cpk(C_S42), cr = cpk(C_R3);
#pragma unroll
            for (int p = 0; p < 16; p++) {
                k3r[p] = h[p];
                ull yv = f2fma(h[p], cb, yn[p * 64]);
                yn[p * 64] = yv;
                ull tv = f2fma(k1[p * 64], c1, yv);
                tv = f2fma(k2[p * 64], c2, tv);
                a[p * 64] = f2fma(h[p], cr, tv);
            }
        }
        // ---- stage 4 ----
        FEVAL();
        {
            const ull cb = cpk(C_B4), c1 = cpk(C_S51), c2 = cpk(C_S52),
                      c3 = cpk(C_S53), cr = cpk(C_R4);
#pragma unroll
            for (int p = 0; p < 16; p++) {
                k4r[p] = h[p];
                ull yv = f2fma(h[p], cb, yn[p * 64]);
                yn[p * 64] = yv;
                ull tv = f2fma(k1[p * 64], c1, yv);
                tv = f2fma(k2[p * 64], c2, tv);
                tv = f2fma(k3r[p], c3, tv);
                a[p * 64] = f2fma(h[p], cr, tv);
            }
        }
        // ---- stage 5 ----
        FEVAL();
        {
            const ull cb = cpk(C_B5), c1 = cpk(C_S61), c2 = cpk(C_S62),
                      c3 = cpk(C_S63), c4 = cpk(C_S64), cr = cpk(C_R5);
#pragma unroll
            for (int p = 0; p < 16; p++) {
                ull yv = f2fma(h[p], cb, yn[p * 64]);
                yn[p * 64] = yv;
                ull tv = f2fma(k1[p * 64], c1, yv);
                tv = f2fma(k2[p * 64], c2, tv);
                tv = f2fma(k3r[p], c3, tv);
                tv = f2fma(k4r[p], c4, tv);
                a[p * 64] = f2fma(h[p], cr, tv);
            }
        }
        // ---- stage 6 ----
        FEVAL();
        {
            const ull cb = cpk(C_B6);
#pragma unroll
            for (int p = 0; p < 16; p++) {
                ull yv = f2fma(h[p], cb, yn[p * 64]);
                yn[p * 64] = yv;
                a[p * 64] = yv;          // next step input = y_new
            }
        }
    }
#undef FEVAL

    // ---- fused decode + integrator epilogue ----
    if (ok) {
        float dec = __ldg(&g_prep[36]);
#pragma unroll
        for (int p = 0; p < 16; p++) {
            float pl = __ldg(&g_prep[4 + 2 * p]);
            float ph = __ldg(&g_prep[5 + 2 * p]);
            float lo, hi;
            upk2(a[p * 64], lo, hi);
            dec = fmaf(lo, pl, fmaf(hi, ph, dec));
        }
        out[i] = dec;
        float vel = nd.y + dec;
        out[OUT_VEL + i] = vel;
        out[OUT_POS + i] = nd.x + vel;
    }
}

extern "C" void kernel_launch(void* const* d_in, const int* in_sizes, int n_in,
                              void* d_out, int out_size) {
    const float* nodes     = (const float*)d_in[0];
    const float* edges     = (const float*)d_in[1];
    const int*   senders   = (const int*)d_in[2];
    const int*   receivers = (const int*)d_in[3];
    const float* globals_  = (const float*)d_in[4];
    const float* encNW     = (const float*)d_in[5];
    const float* encNb     = (const float*)d_in[6];
    const float* encEW     = (const float*)d_in[7];
    const float* encEb     = (const float*)d_in[8];
    const float* odeW1     = (const float*)d_in[9];
    const float* odeb1     = (const float*)d_in[10];
    const float* odeW2     = (const float*)d_in[11];
    const float* odeb2     = (const float*)d_in[12];
    const float* noW       = (const float*)d_in[13];
    const float* nob       = (const float*)d_in[14];
    const float* decNW     = (const float*)d_in[15];
    const float* decNb     = (const float*)d_in[16];
    const float* decEW     = (const float*)d_in[17];
    const float* decEb     = (const float*)d_in[18];
    float* out = (float*)d_out;

    prep_kernel<<<1, 64>>>(encEW, encEb, decEW, decEb, noW, nob, decNW, decNb);
    zero_kernel<<<(2 * NN + 255) / 256, 256>>>();
    edge_kernel<<<(NE + 255) / 256, 256>>>(edges, senders, receivers, out);
    int nblk = (NN + 63) / 64;
    ode_kernel<<<nblk, 64>>>(nodes, globals_, encNW, encNb, encEW, encEb,
                             odeW1, odeb1, odeW2, odeb2, out);
}

// round 6
// speedup vs baseline: 10.8789x; 1.0001x over previous
#include <cuda_runtime.h>
#include <cstdint>

#define NN 100000
#define NE 1600000
#define OUT_DECE (NN)
#define OUT_POS  (NN + NE)
#define OUT_VEL  (NN + NE + NN)

typedef unsigned long long ull;

// ---------------- device-global scratch (no allocations allowed) ----------------
__device__ float4 g_agg[2 * NN];   // [0,NN): sender sums {e0,e1,e2,count}; [NN,2NN): receiver
__device__ float  g_prep[40];      // [0..2]=c_edge, [3]=d_edge, [4..35]=p(node dec), [36]=q

// ---------------- RK coefficients (compile-time, H=0.1 absorbed, rebased on yn) ----
#define C_B1   ((float)(0.1 * (35.0/384.0)))
#define C_B3   ((float)(0.1 * (500.0/1113.0)))
#define C_B4   ((float)(0.1 * (125.0/192.0)))
#define C_B5   ((float)(0.1 * (-2187.0/6784.0)))
#define C_B6   ((float)(0.1 * (11.0/84.0)))
#define C_R1   ((float)(0.1 * (1.0/5.0 - 35.0/384.0)))            // u2: coeff of k1
#define C_S31  ((float)(0.1 * (3.0/40.0 - 35.0/384.0)))           // u3: k1
#define C_R2   ((float)(0.1 * (9.0/40.0)))                        // u3: k2
#define C_S41  ((float)(0.1 * (44.0/45.0 - 35.0/384.0)))          // u4: k1
#define C_S42  ((float)(0.1 * (-56.0/15.0)))                      // u4: k2
#define C_R3   ((float)(0.1 * (32.0/9.0 - 500.0/1113.0)))         // u4: k3
#define C_S51  ((float)(0.1 * (19372.0/6561.0 - 35.0/384.0)))     // u5: k1
#define C_S52  ((float)(0.1 * (-25360.0/2187.0)))                 // u5: k2
#define C_S53  ((float)(0.1 * (64448.0/6561.0 - 500.0/1113.0)))   // u5: k3
#define C_R4   ((float)(0.1 * (-212.0/729.0 - 125.0/192.0)))      // u5: k4
#define C_S61  ((float)(0.1 * (9017.0/3168.0 - 35.0/384.0)))      // u6: k1
#define C_S62  ((float)(0.1 * (-355.0/33.0)))                     // u6: k2
#define C_S63  ((float)(0.1 * (46732.0/5247.0 - 500.0/1113.0)))   // u6: k3
#define C_S64  ((float)(0.1 * (49.0/176.0 - 125.0/192.0)))        // u6: k4
#define C_R5   ((float)(0.1 * (-5103.0/18656.0 + 2187.0/6784.0))) // u6: k5

// ---------------- packed f32x2 helpers ----------------
__device__ __forceinline__ ull pk2(float lo, float hi) {
    ull r;
    asm("mov.b64 %0, {%1, %2};" : "=l"(r) : "r"(__float_as_uint(lo)), "r"(__float_as_uint(hi)));
    return r;
}
__device__ __forceinline__ void upk2(ull v, float& lo, float& hi) {
    unsigned a, b;
    asm("mov.b64 {%0, %1}, %2;" : "=r"(a), "=r"(b) : "l"(v));
    lo = __uint_as_float(a); hi = __uint_as_float(b);
}
__device__ __forceinline__ ull f2fma(ull a, ull b, ull c) {
    ull d;
    asm("fma.rn.f32x2 %0, %1, %2, %3;" : "=l"(d) : "l"(a), "l"(b), "l"(c));
    return d;
}
__device__ __forceinline__ ull cpk(float x) {
    unsigned u = __float_as_uint(x);
    return (((ull)u) << 32) | (ull)u;
}

// ---------------- precompute kernel ----------------
__global__ void prep_kernel(const float* __restrict__ eW, const float* __restrict__ eb,
                            const float* __restrict__ decEW, const float* __restrict__ decEb,
                            const float* __restrict__ noW, const float* __restrict__ nob,
                            const float* __restrict__ decNW, const float* __restrict__ decNb) {
    int t = threadIdx.x;
    if (t < 3) {
        float s = 0.f;
        for (int c = 0; c < 10; c++) s += eW[t * 10 + c] * decEW[c];
        g_prep[t] = s;
    } else if (t == 3) {
        float s = decEb[0];
        for (int c = 0; c < 10; c++) s += eb[c] * decEW[c];
        g_prep[3] = s;
    } else if (t >= 4 && t < 36) {
        int j = t - 4;
        float s = 0.f;
        for (int c = 0; c < 10; c++) s += noW[j * 10 + c] * decNW[c];
        g_prep[t] = s;
    } else if (t == 36) {
        float s = decNb[0];
        for (int c = 0; c < 10; c++) s += nob[c] * decNW[c];
        g_prep[36] = s;
    }
}

__global__ void zero_kernel() {
    int i = blockIdx.x * blockDim.x + threadIdx.x;
    if (i < 2 * NN) g_agg[i] = make_float4(0.f, 0.f, 0.f, 0.f);
}

// ---------------- edge kernel ----------------
__global__ void edge_kernel(const float* __restrict__ edges,
                            const int* __restrict__ senders,
                            const int* __restrict__ receivers,
                            float* __restrict__ out) {
    int e = blockIdx.x * blockDim.x + threadIdx.x;
    if (e >= NE) return;
    float e0 = edges[3 * e + 0];
    float e1 = edges[3 * e + 1];
    float e2 = edges[3 * e + 2];
    int s = senders[e];
    int r = receivers[e];
    float c0 = g_prep[0], c1 = g_prep[1], c2 = g_prep[2], d = g_prep[3];
    out[OUT_DECE + e] = fmaf(e0, c0, fmaf(e1, c1, fmaf(e2, c2, d)));

    float4* ps = &g_agg[s];
    float4* pr = &g_agg[NN + r];
    asm volatile("red.global.add.v4.f32 [%0], {%1, %2, %3, %4};"
                 :: "l"(ps), "f"(e0), "f"(e1), "f"(e2), "f"(1.0f) : "memory");
    asm volatile("red.global.add.v4.f32 [%0], {%1, %2, %3, %4};"
                 :: "l"(pr), "f"(e0), "f"(e1), "f"(e2), "f"(1.0f) : "memory");
}

// ---------------- ODE kernel ----------------
// f(A): h = relu(A@W1+b1) written back to A's smem column; k = A@W2+b2 left in h regs.
// Input vector lives in per-thread SMEM column (stride 64 ull). h[] is the ONLY
// register array, compile-time indexed, live only within one matmul.
__device__ __forceinline__ void mm_s(const float* __restrict__ sW,
                                     const ull* __restrict__ sB,
                                     const ull* __restrict__ vcol, ull h[16]) {
#pragma unroll
    for (int p = 0; p < 16; p++) h[p] = sB[p];
#pragma unroll 1
    for (int ii = 0; ii < 16; ++ii) {
        float lo, hi;
        upk2(vcol[ii * 64], lo, hi);
        ull vlo = pk2(lo, lo);
        ull vhi = pk2(hi, hi);
        const ulonglong2* w0 = reinterpret_cast<const ulonglong2*>(sW + ii * 64);
#pragma unroll
        for (int q = 0; q < 8; q++) {
            ulonglong2 a = w0[q];
            h[2 * q]     = f2fma(a.x, vlo, h[2 * q]);
            h[2 * q + 1] = f2fma(a.y, vlo, h[2 * q + 1]);
        }
        const ulonglong2* w1 = reinterpret_cast<const ulonglong2*>(sW + ii * 64 + 32);
#pragma unroll
        for (int q = 0; q < 8; q++) {
            ulonglong2 a = w1[q];
            h[2 * q]     = f2fma(a.x, vhi, h[2 * q]);
            h[2 * q + 1] = f2fma(a.y, vhi, h[2 * q + 1]);
        }
    }
}

__global__ __launch_bounds__(64)
void ode_kernel(const float* __restrict__ nodes, const float* __restrict__ gl,
                const float* __restrict__ encNW, const float* __restrict__ encNb,
                const float* __restrict__ encEW, const float* __restrict__ encEb,
                const float* __restrict__ W1, const float* __restrict__ b1,
                const float* __restrict__ W2, const float* __restrict__ b2,
                float* __restrict__ out) {
    __shared__ __align__(16) float sW1[1024];
    __shared__ __align__(16) float sW2[1024];
    __shared__ ull sB1[16];
    __shared__ ull sB2[16];
    __shared__ __align__(16) ull sA[16 * 64];    // stage input vector
    __shared__ __align__(16) ull sYn[16 * 64];   // running y accumulator
    __shared__ __align__(16) ull sK1[16 * 64];   // k1
    __shared__ __align__(16) ull sK2[16 * 64];   // k2

    int t = threadIdx.x;   // 0..63
    for (int i = t; i < 1024; i += 64) { sW1[i] = W1[i]; sW2[i] = W2[i]; }
    if (t < 16) {
        sB1[t] = pk2(b1[2 * t], b1[2 * t + 1]);
        sB2[t] = pk2(b2[2 * t], b2[2 * t + 1]);
    }
    __syncthreads();

    int i0 = blockIdx.x * 64 + t;
    bool ok = (i0 < NN);
    int i = ok ? i0 : (NN - 1);

    ull* a  = &sA[t];
    ull* yn = &sYn[t];
    ull* k1 = &sK1[t];
    ull* k2 = &sK2[t];

    // ---- encoder: y = [h_n(10) | sent(10) | recv(10) | g(2)] ----
    float2 nd = reinterpret_cast<const float2*>(nodes)[i];
    float4 sa = g_agg[i];
    float4 ra = g_agg[NN + i];
    {
        float y[32];
#pragma unroll
        for (int c = 0; c < 10; c++) {
            float wn0 = __ldg(&encNW[c]), wn1 = __ldg(&encNW[10 + c]), bn = __ldg(&encNb[c]);
            y[c] = fmaf(nd.x, wn0, fmaf(nd.y, wn1, bn));
            float we0 = __ldg(&encEW[c]), we1 = __ldg(&encEW[10 + c]);
            float we2 = __ldg(&encEW[20 + c]), web = __ldg(&encEb[c]);
            y[10 + c] = fmaf(sa.x, we0, fmaf(sa.y, we1, fmaf(sa.z, we2, sa.w * web)));
            y[20 + c] = fmaf(ra.x, we0, fmaf(ra.y, we1, fmaf(ra.z, we2, ra.w * web)));
        }
        y[30] = gl[0];
        y[31] = gl[1];
#pragma unroll
        for (int p = 0; p < 16; p++) {
            ull v = pk2(y[2 * p], y[2 * p + 1]);
            a[p * 64] = v;
            yn[p * 64] = v;
        }
    }

    ull h[16];        // matmul accumulator (only register array; compile-time indexed)
    ull k3r[16], k4r[16];  // short-lived register copies of k3, k4

    // f: h = A@W1+b1; relu -> back into A column; h = A@W2+b2 (k result in h)
#define FEVAL()                                                         \
    do {                                                                \
        mm_s(sW1, sB1, a, h);                                           \
        _Pragma("unroll")                                               \
        for (int p = 0; p < 16; p++) {                                  \
            float lo, hi;                                               \
            upk2(h[p], lo, hi);                                         \
            a[p * 64] = pk2(fmaxf(lo, 0.f), fmaxf(hi, 0.f));            \
        }                                                               \
        mm_s(sW2, sB2, a, h);                                           \
    } while (0)

#pragma unroll 1
    for (int st = 0; st < 10; ++st) {
        // ---- stage 1 ----
        FEVAL();
        {
            const ull cb = cpk(C_B1), cr = cpk(C_R1);
#pragma unroll
            for (int p = 0; p < 16; p++) {
                k1[p * 64] = h[p];
                ull yv = f2fma(h[p], cb, yn[p * 64]);
                yn[p * 64] = yv;
                a[p * 64] = f2fma(h[p], cr, yv);
            }
        }
        // ---- stage 2 ----
        FEVAL();
        {
            const ull c1 = cpk(C_S31), cr = cpk(C_R2);
#pragma unroll
            for (int p = 0; p < 16; p++) {
                k2[p * 64] = h[p];
                ull tv = f2fma(k1[p * 64], c1, yn[p * 64]);
                a[p * 64] = f2fma(h[p], cr, tv);
            }
        }
        // ---- stage 3 ----
        FEVAL();
        {
            const ull cb = cpk(C_B3), c1 = cpk(C_S41), c2 = cpk(C_S42), cr = cpk(C_R3);
#pragma unroll
            for (int p = 0; p < 16; p++) {
                k3r[p] = h[p];
                ull yv = f2fma(h[p], cb, yn[p * 64]);
                yn[p * 64] = yv;
                ull tv = f2fma(k1[p * 64], c1, yv);
                tv = f2fma(k2[p * 64], c2, tv);
                a[p * 64] = f2fma(h[p], cr, tv);
            }
        }
        // ---- stage 4 ----
        FEVAL();
        {
            const ull cb = cpk(C_B4), c1 = cpk(C_S51), c2 = cpk(C_S52),
                      c3 = cpk(C_S53), cr = cpk(C_R4);
#pragma unroll
            for (int p = 0; p < 16; p++) {
                k4r[p] = h[p];
                ull yv = f2fma(h[p], cb, yn[p * 64]);
                yn[p * 64] = yv;
                ull tv = f2fma(k1[p * 64], c1, yv);
                tv = f2fma(k2[p * 64], c2, tv);
                tv = f2fma(k3r[p], c3, tv);
                a[p * 64] = f2fma(h[p], cr, tv);
            }
        }
        // ---- stage 5 ----
        FEVAL();
        {
            const ull cb = cpk(C_B5), c1 = cpk(C_S61), c2 = cpk(C_S62),
                      c3 = cpk(C_S63), c4 = cpk(C_S64), cr = cpk(C_R5);
#pragma unroll
            for (int p = 0; p < 16; p++) {
                ull yv = f2fma(h[p], cb, yn[p * 64]);
                yn[p * 64] = yv;
                ull tv = f2fma(k1[p * 64], c1, yv);
                tv = f2fma(k2[p * 64], c2, tv);
                tv = f2fma(k3r[p], c3, tv);
                tv = f2fma(k4r[p], c4, tv);
                a[p * 64] = f2fma(h[p], cr, tv);
            }
        }
        // ---- stage 6 ----
        FEVAL();
        {
            const ull cb = cpk(C_B6);
#pragma unroll
            for (int p = 0; p < 16; p++) {
                ull yv = f2fma(h[p], cb, yn[p * 64]);
                yn[p * 64] = yv;
                a[p * 64] = yv;          // next step input = y_new
            }
        }
    }
#undef FEVAL

    // ---- fused decode + integrator epilogue ----
    if (ok) {
        float dec = __ldg(&g_prep[36]);
#pragma unroll
        for (int p = 0; p < 16; p++) {
            float pl = __ldg(&g_prep[4 + 2 * p]);
            float ph = __ldg(&g_prep[5 + 2 * p]);
            float lo, hi;
            upk2(a[p * 64], lo, hi);
            dec = fmaf(lo, pl, fmaf(hi, ph, dec));
        }
        out[i] = dec;
        float vel = nd.y + dec;
        out[OUT_VEL + i] = vel;
        out[OUT_POS + i] = nd.x + vel;
    }
}

extern "C" void kernel_launch(void* const* d_in, const int* in_sizes, int n_in,
                              void* d_out, int out_size) {
    const float* nodes     = (const float*)d_in[0];
    const float* edges     = (const float*)d_in[1];
    const int*   senders   = (const int*)d_in[2];
    const int*   receivers = (const int*)d_in[3];
    const float* globals_  = (const float*)d_in[4];
    const float* encNW     = (const float*)d_in[5];
    const float* encNb     = (const float*)d_in[6];
    const float* encEW     = (const float*)d_in[7];
    const float* encEb     = (const float*)d_in[8];
    const float* odeW1     = (const float*)d_in[9];
    const float* odeb1     = (const float*)d_in[10];
    const float* odeW2     = (const float*)d_in[11];
    const float* odeb2     = (const float*)d_in[12];
    const float* noW       = (const float*)d_in[13];
    const float* nob       = (const float*)d_in[14];
    const float* decNW     = (const float*)d_in[15];
    const float* decNb     = (const float*)d_in[16];
    const float* decEW     = (const float*)d_in[17];
    const float* decEb     = (const float*)d_in[18];
    float* out = (float*)d_out;

    prep_kernel<<<1, 64>>>(encEW, encEb, decEW, decEb, noW, nob, decNW, decNb);
    zero_kernel<<<(2 * NN + 255) / 256, 256>>>();
    edge_kernel<<<(NE + 255) / 256, 256>>>(edges, senders, receivers, out);
    int nblk = (NN + 63) / 64;
    ode_kernel<<<nblk, 64>>>(nodes, globals_, encNW, encNb, encEW, encEb,
                             odeW1, odeb1, odeW2, odeb2, out);
}

// round 9
// speedup vs baseline: 27.8154x; 2.5568x over previous
#include <cuda_runtime.h>
#include <cuda_bf16.h>
#include <cstdint>

#define NN 100000
#define NE 1600000
#define OUT_DECE (NN)
#define OUT_POS  (NN + NE)
#define OUT_VEL  (NN + NE + NN)

// ---------------- device-global scratch ----------------
__device__ float4 g_agg[2 * NN];
__device__ float  g_prep[40];
// split bf16 weights: [l][n(32)][k(64)]: k<32 = hi(W[k][n]), k>=32 = lo residual
__device__ __align__(16) unsigned short g_wcat[2 * 32 * 64];

// ---------------- RK coefficients (H=0.1 absorbed, rebased on yn) ----------------
#define C_B1   ((float)(0.1 * (35.0/384.0)))
#define C_B3   ((float)(0.1 * (500.0/1113.0)))
#define C_B4   ((float)(0.1 * (125.0/192.0)))
#define C_B5   ((float)(0.1 * (-2187.0/6784.0)))
#define C_B6   ((float)(0.1 * (11.0/84.0)))
#define C_R1   ((float)(0.1 * (1.0/5.0 - 35.0/384.0)))
#define C_S31  ((float)(0.1 * (3.0/40.0 - 35.0/384.0)))
#define C_R2   ((float)(0.1 * (9.0/40.0)))
#define C_S41  ((float)(0.1 * (44.0/45.0 - 35.0/384.0)))
#define C_S42  ((float)(0.1 * (-56.0/15.0)))
#define C_R3   ((float)(0.1 * (32.0/9.0 - 500.0/1113.0)))
#define C_S51  ((float)(0.1 * (19372.0/6561.0 - 35.0/384.0)))
#define C_S52  ((float)(0.1 * (-25360.0/2187.0)))
#define C_S53  ((float)(0.1 * (64448.0/6561.0 - 500.0/1113.0)))
#define C_R4   ((float)(0.1 * (-212.0/729.0 - 125.0/192.0)))
#define C_S61  ((float)(0.1 * (9017.0/3168.0 - 35.0/384.0)))
#define C_S62  ((float)(0.1 * (-355.0/33.0)))
#define C_S63  ((float)(0.1 * (46732.0/5247.0 - 500.0/1113.0)))
#define C_S64  ((float)(0.1 * (49.0/176.0 - 125.0/192.0)))
#define C_R5   ((float)(0.1 * (-5103.0/18656.0 + 2187.0/6784.0)))

// ---------------- helpers ----------------
__device__ __forceinline__ uint32_t smem_u32(const void* p) {
    uint32_t a;
    asm("{ .reg .u64 t; cvta.to.shared.u64 t, %1; cvt.u32.u64 %0, t; }" : "=r"(a) : "l"(p));
    return a;
}
#define SW128(o) ((uint32_t)(o) ^ ((((uint32_t)(o)) >> 3) & 0x70u))

// pack (lo, hi) floats -> bf16x2 (lo in low 16 bits)
__device__ __forceinline__ uint32_t pkbf(float lo, float hi) {
    uint32_t r;
    asm("cvt.rn.bf16x2.f32 %0, %1, %2;" : "=r"(r) : "f"(hi), "f"(lo));
    return r;
}

__device__ __forceinline__ void ldm4(uint32_t a[4], uint32_t addr) {
    asm volatile("ldmatrix.sync.aligned.m8n8.x4.shared.b16 {%0,%1,%2,%3}, [%4];"
                 : "=r"(a[0]), "=r"(a[1]), "=r"(a[2]), "=r"(a[3]) : "r"(addr));
}
__device__ __forceinline__ void mma16816(float d[4], const uint32_t a[4], const uint32_t b[2]) {
    asm volatile("mma.sync.aligned.m16n8k16.row.col.f32.bf16.bf16.f32 "
                 "{%0,%1,%2,%3}, {%4,%5,%6,%7}, {%8,%9}, {%0,%1,%2,%3};"
                 : "+f"(d[0]), "+f"(d[1]), "+f"(d[2]), "+f"(d[3])
                 : "r"(a[0]), "r"(a[1]), "r"(a[2]), "r"(a[3]), "r"(b[0]), "r"(b[1]));
}

// ldmatrix address: A-tile rows 128 x 128B, SW128. tile (mt,kt) for warp row-base rb.
__device__ __forceinline__ uint32_t amat_addr(uint32_t sbA, int rb, int mt, int kt, int lane) {
    int sub = lane >> 3, r = lane & 7;
    uint32_t row = (uint32_t)(rb + mt * 16 + (sub & 1) * 8 + r);
    uint32_t off = row * 128u + (uint32_t)(kt * 32 + (sub >> 1) * 16);
    return sbA + SW128(off);
}

// store hi/lo split pair for channels (c0, c0+1) of row into A-tile
__device__ __forceinline__ void store_pair(uint32_t sbA, int row, int c0, float v0, float v1) {
    uint32_t hp = pkbf(v0, v1);
    float r0 = v0 - __uint_as_float(hp << 16);
    float r1 = v1 - __uint_as_float(hp & 0xFFFF0000u);
    uint32_t lp = pkbf(r0, r1);
    uint32_t off = (uint32_t)row * 128u + (uint32_t)c0 * 2u;
    uint32_t offl = off + 64u;
    uint32_t ah = sbA + SW128(off);
    uint32_t al = sbA + SW128(offl);
    asm volatile("st.shared.b32 [%0], %1;" :: "r"(ah), "r"(hp) : "memory");
    asm volatile("st.shared.b32 [%0], %1;" :: "r"(al), "r"(lp) : "memory");
}

// ---------------- precompute kernel ----------------
__global__ void prep_kernel(const float* __restrict__ eW, const float* __restrict__ eb,
                            const float* __restrict__ decEW, const float* __restrict__ decEb,
                            const float* __restrict__ noW, const float* __restrict__ nob,
                            const float* __restrict__ decNW, const float* __restrict__ decNb,
                            const float* __restrict__ odeW1, const float* __restrict__ odeW2) {
    int t = threadIdx.x;   // 128
    if (t < 3) {
        float s = 0.f;
        for (int c = 0; c < 10; c++) s += eW[t * 10 + c] * decEW[c];
        g_prep[t] = s;
    } else if (t == 3) {
        float s = decEb[0];
        for (int c = 0; c < 10; c++) s += eb[c] * decEW[c];
        g_prep[3] = s;
    } else if (t >= 4 && t < 36) {
        int j = t - 4;
        float s = 0.f;
        for (int c = 0; c < 10; c++) s += noW[j * 10 + c] * decNW[c];
        g_prep[t] = s;
    } else if (t == 36) {
        float s = decNb[0];
        for (int c = 0; c < 10; c++) s += nob[c] * decNW[c];
        g_prep[36] = s;
    }
    if (t < 64) {
        int l = t >> 5, n = t & 31;
        const float* W = l ? odeW2 : odeW1;
        unsigned short* dst = &g_wcat[l * 2048 + n * 64];
        for (int kk = 0; kk < 32; kk++) {
            float f = W[kk * 32 + n];
            __nv_bfloat16 hi = __float2bfloat16(f);
            __nv_bfloat16 lo = __float2bfloat16(f - __bfloat162float(hi));
            dst[kk]      = __bfloat16_as_ushort(hi);
            dst[32 + kk] = __bfloat16_as_ushort(lo);
        }
    }
}

__global__ void zero_kernel() {
    int i = blockIdx.x * blockDim.x + threadIdx.x;
    if (i < 2 * NN) g_agg[i] = make_float4(0.f, 0.f, 0.f, 0.f);
}

// ---------------- edge kernel ----------------
__global__ void edge_kernel(const float* __restrict__ edges,
                            const int* __restrict__ senders,
                            const int* __restrict__ receivers,
                            float* __restrict__ out) {
    int e = blockIdx.x * blockDim.x + threadIdx.x;
    if (e >= NE) return;
    float e0 = edges[3 * e + 0];
    float e1 = edges[3 * e + 1];
    float e2 = edges[3 * e + 2];
    int s = senders[e];
    int r = receivers[e];
    float c0 = g_prep[0], c1 = g_prep[1], c2 = g_prep[2], d = g_prep[3];
    out[OUT_DECE + e] = fmaf(e0, c0, fmaf(e1, c1, fmaf(e2, c2, d)));
    float4* ps = &g_agg[s];
    float4* pr = &g_agg[NN + r];
    asm volatile("red.global.add.v4.f32 [%0], {%1, %2, %3, %4};"
                 :: "l"(ps), "f"(e0), "f"(e1), "f"(e2), "f"(1.0f) : "memory");
    asm volatile("red.global.add.v4.f32 [%0], {%1, %2, %3, %4};"
                 :: "l"(pr), "f"(e0), "f"(e1), "f"(e2), "f"(1.0f) : "memory");
}

// ---------------- smem layout (dynamic) ----------------
#define SM_A    0
#define SM_K1   16384
#define SM_K2   (SM_K1 + 16384)
#define SM_K3   (SM_K2 + 16384)
#define SM_K4   (SM_K3 + 16384)
#define SM_TOTAL (SM_K4 + 16384)   /* 80 KB */

// f-eval for one 16-row m-tile: kv = f(u) where A-tile holds split(u) rows of mt.
__device__ __forceinline__ void feval_mt(uint32_t sbA, int rb, int mt, int lane, int g, int q,
                                         const uint32_t (&bw)[2][4][4][2],
                                         const float (&b1)[4][2], const float (&b2)[4][2],
                                         float (&kv)[4][4]) {
    __syncwarp();
    uint32_t a0[4], a1[4], a2[4], a3[4];
    ldm4(a0, amat_addr(sbA, rb, mt, 0, lane));
    ldm4(a1, amat_addr(sbA, rb, mt, 1, lane));
    ldm4(a2, amat_addr(sbA, rb, mt, 2, lane));
    ldm4(a3, amat_addr(sbA, rb, mt, 3, lane));
    float d[4][4];
#pragma unroll
    for (int nt = 0; nt < 4; nt++) {
#pragma unroll
        for (int ii = 0; ii < 4; ii++) d[nt][ii] = 0.f;
        mma16816(d[nt], a0, bw[0][0][nt]);   // hi * Whi
        mma16816(d[nt], a1, bw[0][1][nt]);
        mma16816(d[nt], a2, bw[0][2][nt]);   // lo * Wlo
        mma16816(d[nt], a3, bw[0][3][nt]);
        mma16816(d[nt], a0, bw[0][2][nt]);   // hi * Wlo
        mma16816(d[nt], a1, bw[0][3][nt]);
        mma16816(d[nt], a2, bw[0][0][nt]);   // lo * Whi
        mma16816(d[nt], a3, bw[0][1][nt]);
    }
    // h = relu(d + b1) -> split back into A-tile (same rows)
    int rA = rb + mt * 16 + g;
#pragma unroll
    for (int nt = 0; nt < 4; nt++) {
        float v0 = fmaxf(d[nt][0] + b1[nt][0], 0.f);
        float v1 = fmaxf(d[nt][1] + b1[nt][1], 0.f);
        float v2 = fmaxf(d[nt][2] + b1[nt][0], 0.f);
        float v3 = fmaxf(d[nt][3] + b1[nt][1], 0.f);
        store_pair(sbA, rA, nt * 8 + 2 * q, v0, v1);
        store_pair(sbA, rA + 8, nt * 8 + 2 * q, v2, v3);
    }
    __syncwarp();
    // layer 2
    ldm4(a0, amat_addr(sbA, rb, mt, 0, lane));
    ldm4(a1, amat_addr(sbA, rb, mt, 1, lane));
    ldm4(a2, amat_addr(sbA, rb, mt, 2, lane));
    ldm4(a3, amat_addr(sbA, rb, mt, 3, lane));
#pragma unroll
    for (int nt = 0; nt < 4; nt++) {
#pragma unroll
        for (int ii = 0; ii < 4; ii++) kv[nt][ii] = 0.f;
        mma16816(kv[nt], a0, bw[1][0][nt]);
        mma16816(kv[nt], a1, bw[1][1][nt]);
        mma16816(kv[nt], a2, bw[1][2][nt]);
        mma16816(kv[nt], a3, bw[1][3][nt]);
        mma16816(kv[nt], a0, bw[1][2][nt]);
        mma16816(kv[nt], a1, bw[1][3][nt]);
        mma16816(kv[nt], a2, bw[1][0][nt]);
        mma16816(kv[nt], a3, bw[1][1][nt]);
        kv[nt][0] += b2[nt][0];
        kv[nt][1] += b2[nt][1];
        kv[nt][2] += b2[nt][0];
        kv[nt][3] += b2[nt][1];
    }
}

// RK stage frame: run both m-tiles, apply BODY per fragment element, store next u
#define RK_FRAME(BODY)                                                        \
    _Pragma("unroll")                                                         \
    for (int mt = 0; mt < 2; mt++) {                                          \
        float kv[4][4];                                                       \
        feval_mt(sbA, rb, mt, lane, g, q, bw, bias1, bias2, kv);              \
        int rA = rb + mt * 16 + g;                                            \
        _Pragma("unroll")                                                     \
        for (int nt = 0; nt < 4; nt++) {                                      \
            float uu[4];                                                      \
            _Pragma("unroll")                                                 \
            for (int ii = 0; ii < 4; ii++) {                                  \
                int cg = (mt * 16 + nt * 4 + ii) * 128 + t;                   \
                float k = kv[nt][ii];                                         \
                float Y = yn[mt][nt][ii];                                     \
                BODY                                                          \
                yn[mt][nt][ii] = Y;                                           \
            }                                                                 \
            store_pair(sbA, rA, nt * 8 + 2 * q, uu[0], uu[1]);                \
            store_pair(sbA, rA + 8, nt * 8 + 2 * q, uu[2], uu[3]);            \
        }                                                                     \
    }

__global__ __launch_bounds__(128)
void ode_kernel(const float* __restrict__ nodes, const float* __restrict__ gl,
                const float* __restrict__ encNW, const float* __restrict__ encNb,
                const float* __restrict__ encEW, const float* __restrict__ encEb,
                const float* __restrict__ b1g, const float* __restrict__ b2g,
                float* __restrict__ out) {
    extern __shared__ char sm[];
    uint32_t sb = smem_u32(sm);
    uint32_t sbA = sb + SM_A;
    int t = threadIdx.x;
    int w = t >> 5, lane = t & 31;
    int g = lane >> 2, q = lane & 3;
    int rb = w * 32;
    int cbase = blockIdx.x * 128;

    // ---- load B weight fragments (register-stationary) ----
    uint32_t bw[2][4][4][2];
#pragma unroll
    for (int l = 0; l < 2; l++)
#pragma unroll
        for (int k8 = 0; k8 < 4; k8++)
#pragma unroll
            for (int nt = 0; nt < 4; nt++) {
                int n = nt * 8 + g;
                const unsigned short* src = g_wcat + l * 2048 + n * 64 + k8 * 16 + 2 * q;
                bw[l][k8][nt][0] = *(const uint32_t*)(src);
                bw[l][k8][nt][1] = *(const uint32_t*)(src + 8);
            }
    float bias1[4][2], bias2[4][2], pdec[4][2];
#pragma unroll
    for (int nt = 0; nt < 4; nt++) {
        int c = nt * 8 + 2 * q;
        bias1[nt][0] = __ldg(&b1g[c]);     bias1[nt][1] = __ldg(&b1g[c + 1]);
        bias2[nt][0] = __ldg(&b2g[c]);     bias2[nt][1] = __ldg(&b2g[c + 1]);
        pdec[nt][0]  = __ldg(&g_prep[4 + c]);
        pdec[nt][1]  = __ldg(&g_prep[5 + c]);
    }

    // ---- encoder for this thread's node (row t) ----
    int i0 = cbase + t;
    int i = (i0 < NN) ? i0 : (NN - 1);
    float2 nd = reinterpret_cast<const float2*>(nodes)[i];
    float4 sa = g_agg[i];
    float4 ra = g_agg[NN + i];
    float u0[32];
#pragma unroll
    for (int c = 0; c < 10; c++) {
        float wn0 = __ldg(&encNW[c]), wn1 = __ldg(&encNW[10 + c]), bn = __ldg(&encNb[c]);
        u0[c] = fmaf(nd.x, wn0, fmaf(nd.y, wn1, bn));
        float we0 = __ldg(&encEW[c]), we1 = __ldg(&encEW[10 + c]);
        float we2 = __ldg(&encEW[20 + c]), web = __ldg(&encEb[c]);
        u0[10 + c] = fmaf(sa.x, we0, fmaf(sa.y, we1, fmaf(sa.z, we2, sa.w * web)));
        u0[20 + c] = fmaf(ra.x, we0, fmaf(ra.y, we1, fmaf(ra.z, we2, ra.w * web)));
    }
    u0[30] = gl[0];
    u0[31] = gl[1];

    // write split(u0) to A-tile row t (v4-vectorized)
    {
        uint32_t rbyte = (uint32_t)t * 128u;
#pragma unroll
        for (int gq = 0; gq < 4; gq++) {
            uint32_t hh[4], ll[4];
#pragma unroll
            for (int p = 0; p < 4; p++) {
                float a = u0[gq * 8 + 2 * p], b = u0[gq * 8 + 2 * p + 1];
                uint32_t hp = pkbf(a, b);
                float r0 = a - __uint_as_float(hp << 16);
                float r1 = b - __uint_as_float(hp & 0xFFFF0000u);
                hh[p] = hp;
                ll[p] = pkbf(r0, r1);
            }
            uint32_t ah = sbA + SW128(rbyte + gq * 16);
            asm volatile("st.shared.v4.b32 [%0], {%1,%2,%3,%4};"
                         :: "r"(ah), "r"(hh[0]), "r"(hh[1]), "r"(hh[2]), "r"(hh[3]) : "memory");
            uint32_t al = sbA + SW128(rbyte + 64 + gq * 16);
            asm volatile("st.shared.v4.b32 [%0], {%1,%2,%3,%4};"
                         :: "r"(al), "r"(ll[0]), "r"(ll[1]), "r"(ll[2]), "r"(ll[3]) : "memory");
        }
    }
    // stage u0 (fp32) into K1 region as scr[col*128 + rowLocal] for yn-frag init
    float* scr = (float*)(sm + SM_K1);
#pragma unroll
    for (int c = 0; c < 32; c++) scr[c * 128 + t] = u0[c];
    __syncwarp();

    float yn[2][4][4];
#pragma unroll
    for (int mt = 0; mt < 2; mt++)
#pragma unroll
        for (int nt = 0; nt < 4; nt++)
#pragma unroll
            for (int ii = 0; ii < 4; ii++) {
                int row = rb + mt * 16 + (ii >> 1) * 8 + g;
                int col = nt * 8 + 2 * q + (ii & 1);
                yn[mt][nt][ii] = scr[col * 128 + row];
            }
    __syncwarp();

    float* k1s = (float*)(sm + SM_K1);
    float* k2s = (float*)(sm + SM_K2);
    float* k3s = (float*)(sm + SM_K3);
    float* k4s = (float*)(sm + SM_K4);

#pragma unroll 1
    for (int st = 0; st < 10; ++st) {
        RK_FRAME({ k1s[cg] = k; Y = fmaf(k, C_B1, Y); uu[ii] = fmaf(k, C_R1, Y); })
        RK_FRAME({ k2s[cg] = k; float tv = fmaf(k1s[cg], C_S31, Y); uu[ii] = fmaf(k, C_R2, tv); })
        RK_FRAME({ k3s[cg] = k; Y = fmaf(k, C_B3, Y);
                   float tv = fmaf(k1s[cg], C_S41, Y);
                   tv = fmaf(k2s[cg], C_S42, tv);
                   uu[ii] = fmaf(k, C_R3, tv); })
        RK_FRAME({ k4s[cg] = k; Y = fmaf(k, C_B4, Y);
                   float tv = fmaf(k1s[cg], C_S51, Y);
                   tv = fmaf(k2s[cg], C_S52, tv);
                   tv = fmaf(k3s[cg], C_S53, tv);
                   uu[ii] = fmaf(k, C_R4, tv); })
        RK_FRAME({ Y = fmaf(k, C_B5, Y);
                   float tv = fmaf(k1s[cg], C_S61, Y);
                   tv = fmaf(k2s[cg], C_S62, tv);
                   tv = fmaf(k3s[cg], C_S63, tv);
                   tv = fmaf(k4s[cg], C_S64, tv);
                   uu[ii] = fmaf(k, C_R5, tv); })
        RK_FRAME({ Y = fmaf(k, C_B6, Y); uu[ii] = Y; })
    }

    // ---- decode + integrator epilogue (frag space, shfl row-reduce) ----
    float qc = __ldg(&g_prep[36]);
#pragma unroll
    for (int mt = 0; mt < 2; mt++) {
        float s1 = 0.f, s2 = 0.f;
#pragma unroll
        for (int nt = 0; nt < 4; nt++) {
            s1 = fmaf(yn[mt][nt][0], pdec[nt][0], fmaf(yn[mt][nt][1], pdec[nt][1], s1));
            s2 = fmaf(yn[mt][nt][2], pdec[nt][0], fmaf(yn[mt][nt][3], pdec[nt][1], s2));
        }
        s1 += __shfl_xor_sync(0xFFFFFFFFu, s1, 1);
        s1 += __shfl_xor_sync(0xFFFFFFFFu, s1, 2);
        s2 += __shfl_xor_sync(0xFFFFFFFFu, s2, 1);
        s2 += __shfl_xor_sync(0xFFFFFFFFu, s2, 2);
        if (q == 0) {
            int iA = cbase + rb + mt * 16 + g;
            int iB = iA + 8;
            if (iA < NN) {
                float2 n2 = reinterpret_cast<const float2*>(nodes)[iA];
                float dec = s1 + qc;
                out[iA] = dec;
                float vel = n2.y + dec;
                out[OUT_VEL + iA] = vel;
                out[OUT_POS + iA] = n2.x + vel;
            }
            if (iB < NN) {
                float2 n2 = reinterpret_cast<const float2*>(nodes)[iB];
                float dec = s2 + qc;
                out[iB] = dec;
                float vel = n2.y + dec;
                out[OUT_VEL + iB] = vel;
                out[OUT_POS + iB] = n2.x + vel;
            }
        }
    }
}

extern "C" void kernel_launch(void* const* d_in, const int* in_sizes, int n_in,
                              void* d_out, int out_size) {
    const float* nodes     = (const float*)d_in[0];
    const float* edges     = (const float*)d_in[1];
    const int*   senders   = (const int*)d_in[2];
    const int*   receivers = (const int*)d_in[3];
    const float* globals_  = (const float*)d_in[4];
    const float* encNW     = (const float*)d_in[5];
    const float* encNb     = (const float*)d_in[6];
    const float* encEW     = (const float*)d_in[7];
    const float* encEb     = (const float*)d_in[8];
    const float* odeW1     = (const float*)d_in[9];
    const float* odeb1     = (const float*)d_in[10];
    const float* odeW2     = (const float*)d_in[11];
    const float* odeb2     = (const float*)d_in[12];
    const float* noW       = (const float*)d_in[13];
    const float* nob       = (const float*)d_in[14];
    const float* decNW     = (const float*)d_in[15];
    const float* decNb     = (const float*)d_in[16];
    const float* decEW     = (const float*)d_in[17];
    const float* decEb     = (const float*)d_in[18];
    float* out = (float*)d_out;

    cudaFuncSetAttribute(ode_kernel, cudaFuncAttributeMaxDynamicSharedMemorySize, SM_TOTAL);

    prep_kernel<<<1, 128>>>(encEW, encEb, decEW, decEb, noW, nob, decNW, decNb,
                            odeW1, odeW2);
    zero_kernel<<<(2 * NN + 255) / 256, 256>>>();
    edge_kernel<<<(NE + 255) / 256, 256>>>(edges, senders, receivers, out);
    int nblk = (NN + 127) / 128;
    ode_kernel<<<nblk, 128, SM_TOTAL>>>(nodes, globals_, encNW, encNb, encEW, encEb,
                                        odeb1, odeb2, out);
}

// round 10
// speedup vs baseline: 31.5860x; 1.1356x over previous
#include <cuda_runtime.h>
#include <cuda_bf16.h>
#include <cstdint>

#define NN 100000
#define NE 1600000
#define OUT_DECE (NN)
#define OUT_POS  (NN + NE)
#define OUT_VEL  (NN + NE + NN)

// ---------------- device-global scratch ----------------
__device__ float4 g_agg[2 * NN];
__device__ float  g_prep[40];
// split bf16 weights: [l][n(32)][k(64)]: k<32 = hi(W[k][n]), k>=32 = lo residual
__device__ __align__(16) unsigned short g_wcat[2 * 32 * 64];

// ---------------- RK coefficients (H=0.1 absorbed, rebased on yn) ----------------
#define C_B1   ((float)(0.1 * (35.0/384.0)))
#define C_B3   ((float)(0.1 * (500.0/1113.0)))
#define C_B4   ((float)(0.1 * (125.0/192.0)))
#define C_B5   ((float)(0.1 * (-2187.0/6784.0)))
#define C_B6   ((float)(0.1 * (11.0/84.0)))
#define C_R1   ((float)(0.1 * (1.0/5.0 - 35.0/384.0)))
#define C_S31  ((float)(0.1 * (3.0/40.0 - 35.0/384.0)))
#define C_R2   ((float)(0.1 * (9.0/40.0)))
#define C_S41  ((float)(0.1 * (44.0/45.0 - 35.0/384.0)))
#define C_S42  ((float)(0.1 * (-56.0/15.0)))
#define C_R3   ((float)(0.1 * (32.0/9.0 - 500.0/1113.0)))
#define C_S51  ((float)(0.1 * (19372.0/6561.0 - 35.0/384.0)))
#define C_S52  ((float)(0.1 * (-25360.0/2187.0)))
#define C_S53  ((float)(0.1 * (64448.0/6561.0 - 500.0/1113.0)))
#define C_R4   ((float)(0.1 * (-212.0/729.0 - 125.0/192.0)))
#define C_S61  ((float)(0.1 * (9017.0/3168.0 - 35.0/384.0)))
#define C_S62  ((float)(0.1 * (-355.0/33.0)))
#define C_S63  ((float)(0.1 * (46732.0/5247.0 - 500.0/1113.0)))
#define C_S64  ((float)(0.1 * (49.0/176.0 - 125.0/192.0)))
#define C_R5   ((float)(0.1 * (-5103.0/18656.0 + 2187.0/6784.0)))

// ---------------- helpers ----------------
__device__ __forceinline__ uint32_t smem_u32(const void* p) {
    uint32_t a;
    asm("{ .reg .u64 t; cvta.to.shared.u64 t, %1; cvt.u32.u64 %0, t; }" : "=r"(a) : "l"(p));
    return a;
}
#define SW128(o) ((uint32_t)(o) ^ ((((uint32_t)(o)) >> 3) & 0x70u))

// pack (lo, hi) floats -> bf16x2 (lo in low 16 bits)
__device__ __forceinline__ uint32_t pkbf(float lo, float hi) {
    uint32_t r;
    asm("cvt.rn.bf16x2.f32 %0, %1, %2;" : "=r"(r) : "f"(hi), "f"(lo));
    return r;
}

__device__ __forceinline__ void ldm4(uint32_t a[4], uint32_t addr) {
    asm volatile("ldmatrix.sync.aligned.m8n8.x4.shared.b16 {%0,%1,%2,%3}, [%4];"
                 : "=r"(a[0]), "=r"(a[1]), "=r"(a[2]), "=r"(a[3]) : "r"(addr));
}
__device__ __forceinline__ void mma16816(float d[4], const uint32_t a[4], const uint32_t b[2]) {
    asm volatile("mma.sync.aligned.m16n8k16.row.col.f32.bf16.bf16.f32 "
                 "{%0,%1,%2,%3}, {%4,%5,%6,%7}, {%8,%9}, {%0,%1,%2,%3};"
                 : "+f"(d[0]), "+f"(d[1]), "+f"(d[2]), "+f"(d[3])
                 : "r"(a[0]), "r"(a[1]), "r"(a[2]), "r"(a[3]), "r"(b[0]), "r"(b[1]));
}

// ldmatrix address: A-tile rows 128 x 128B, SW128. tile (mt,kt) for warp row-base rb.
__device__ __forceinline__ uint32_t amat_addr(uint32_t sbA, int rb, int mt, int kt, int lane) {
    int sub = lane >> 3, r = lane & 7;
    uint32_t row = (uint32_t)(rb + mt * 16 + (sub & 1) * 8 + r);
    uint32_t off = row * 128u + (uint32_t)(kt * 32 + (sub >> 1) * 16);
    return sbA + SW128(off);
}

// store hi/lo split pair for channels (c0, c0+1) of row into A-tile
__device__ __forceinline__ void store_pair(uint32_t sbA, int row, int c0, float v0, float v1) {
    uint32_t hp = pkbf(v0, v1);
    float r0 = v0 - __uint_as_float(hp << 16);
    float r1 = v1 - __uint_as_float(hp & 0xFFFF0000u);
    uint32_t lp = pkbf(r0, r1);
    uint32_t off = (uint32_t)row * 128u + (uint32_t)c0 * 2u;
    uint32_t offl = off + 64u;
    uint32_t ah = sbA + SW128(off);
    uint32_t al = sbA + SW128(offl);
    asm volatile("st.shared.b32 [%0], %1;" :: "r"(ah), "r"(hp) : "memory");
    asm volatile("st.shared.b32 [%0], %1;" :: "r"(al), "r"(lp) : "memory");
}

// ---------------- precompute kernel ----------------
__global__ void prep_kernel(const float* __restrict__ eW, const float* __restrict__ eb,
                            const float* __restrict__ decEW, const float* __restrict__ decEb,
                            const float* __restrict__ noW, const float* __restrict__ nob,
                            const float* __restrict__ decNW, const float* __restrict__ decNb,
                            const float* __restrict__ odeW1, const float* __restrict__ odeW2) {
    int t = threadIdx.x;   // 128
    if (t < 3) {
        float s = 0.f;
        for (int c = 0; c < 10; c++) s += eW[t * 10 + c] * decEW[c];
        g_prep[t] = s;
    } else if (t == 3) {
        float s = decEb[0];
        for (int c = 0; c < 10; c++) s += eb[c] * decEW[c];
        g_prep[3] = s;
    } else if (t >= 4 && t < 36) {
        int j = t - 4;
        float s = 0.f;
        for (int c = 0; c < 10; c++) s += noW[j * 10 + c] * decNW[c];
        g_prep[t] = s;
    } else if (t == 36) {
        float s = decNb[0];
        for (int c = 0; c < 10; c++) s += nob[c] * decNW[c];
        g_prep[36] = s;
    }
    if (t < 64) {
        int l = t >> 5, n = t & 31;
        const float* W = l ? odeW2 : odeW1;
        unsigned short* dst = &g_wcat[l * 2048 + n * 64];
        for (int kk = 0; kk < 32; kk++) {
            float f = W[kk * 32 + n];
            __nv_bfloat16 hi = __float2bfloat16(f);
            __nv_bfloat16 lo = __float2bfloat16(f - __bfloat162float(hi));
            dst[kk]      = __bfloat16_as_ushort(hi);
            dst[32 + kk] = __bfloat16_as_ushort(lo);
        }
    }
}

__global__ void zero_kernel() {
    int i = blockIdx.x * blockDim.x + threadIdx.x;
    if (i < 2 * NN) g_agg[i] = make_float4(0.f, 0.f, 0.f, 0.f);
}

// ---------------- edge kernel ----------------
__global__ void edge_kernel(const float* __restrict__ edges,
                            const int* __restrict__ senders,
                            const int* __restrict__ receivers,
                            float* __restrict__ out) {
    int e = blockIdx.x * blockDim.x + threadIdx.x;
    if (e >= NE) return;
    float e0 = edges[3 * e + 0];
    float e1 = edges[3 * e + 1];
    float e2 = edges[3 * e + 2];
    int s = senders[e];
    int r = receivers[e];
    float c0 = g_prep[0], c1 = g_prep[1], c2 = g_prep[2], d = g_prep[3];
    out[OUT_DECE + e] = fmaf(e0, c0, fmaf(e1, c1, fmaf(e2, c2, d)));
    float4* ps = &g_agg[s];
    float4* pr = &g_agg[NN + r];
    asm volatile("red.global.add.v4.f32 [%0], {%1, %2, %3, %4};"
                 :: "l"(ps), "f"(e0), "f"(e1), "f"(e2), "f"(1.0f) : "memory");
    asm volatile("red.global.add.v4.f32 [%0], {%1, %2, %3, %4};"
                 :: "l"(pr), "f"(e0), "f"(e1), "f"(e2), "f"(1.0f) : "memory");
}

// ---------------- smem layout (dynamic) ----------------
#define SM_A    0
#define SM_K1   16384
#define SM_K2   (SM_K1 + 16384)
#define SM_K3   (SM_K2 + 16384)
#define SM_K4   (SM_K3 + 16384)
#define SM_TOTAL (SM_K4 + 16384)   /* 80 KB */

// 6-MMA split chain (hi*Whi + hi*Wlo + lo*Whi; lo*Wlo dropped, ~2^-18 rel)
#define CHAIN6(D, A, BL, NT)                   \
    do {                                       \
        mma16816(D, (A)[0], bw[BL][0][NT]);    \
        mma16816(D, (A)[1], bw[BL][1][NT]);    \
        mma16816(D, (A)[0], bw[BL][2][NT]);    \
        mma16816(D, (A)[1], bw[BL][3][NT]);    \
        mma16816(D, (A)[2], bw[BL][0][NT]);    \
        mma16816(D, (A)[3], bw[BL][1][NT]);    \
    } while (0)

// fused f-eval over BOTH m-tiles: kv = f(u). 8 independent MMA chains per layer.
__device__ __forceinline__ void feval2(uint32_t sbA, int rb, int lane, int g, int q,
                                       const uint32_t (&bw)[2][4][4][2],
                                       const float (&b1)[4][2], const float (&b2)[4][2],
                                       float (&kv)[2][4][4]) {
    __syncwarp();
    uint32_t A[2][4][4];
#pragma unroll
    for (int mt = 0; mt < 2; mt++)
#pragma unroll
        for (int kt = 0; kt < 4; kt++) ldm4(A[mt][kt], amat_addr(sbA, rb, mt, kt, lane));
    {
        float d[2][4][4];
#pragma unroll
        for (int mt = 0; mt < 2; mt++)
#pragma unroll
            for (int nt = 0; nt < 4; nt++) {
#pragma unroll
                for (int ii = 0; ii < 4; ii++) d[mt][nt][ii] = 0.f;
                CHAIN6(d[mt][nt], A[mt], 0, nt);
            }
        // h = relu(d + b1) -> split back into A-tile
#pragma unroll
        for (int mt = 0; mt < 2; mt++) {
            int rA = rb + mt * 16 + g;
#pragma unroll
            for (int nt = 0; nt < 4; nt++) {
                float v0 = fmaxf(d[mt][nt][0] + b1[nt][0], 0.f);
                float v1 = fmaxf(d[mt][nt][1] + b1[nt][1], 0.f);
                float v2 = fmaxf(d[mt][nt][2] + b1[nt][0], 0.f);
                float v3 = fmaxf(d[mt][nt][3] + b1[nt][1], 0.f);
                store_pair(sbA, rA, nt * 8 + 2 * q, v0, v1);
                store_pair(sbA, rA + 8, nt * 8 + 2 * q, v2, v3);
            }
        }
    }
    __syncwarp();
#pragma unroll
    for (int mt = 0; mt < 2; mt++)
#pragma unroll
        for (int kt = 0; kt < 4; kt++) ldm4(A[mt][kt], amat_addr(sbA, rb, mt, kt, lane));
#pragma unroll
    for (int mt = 0; mt < 2; mt++)
#pragma unroll
        for (int nt = 0; nt < 4; nt++) {
#pragma unroll
            for (int ii = 0; ii < 4; ii++) kv[mt][nt][ii] = 0.f;
            CHAIN6(kv[mt][nt], A[mt], 1, nt);
            kv[mt][nt][0] += b2[nt][0];
            kv[mt][nt][1] += b2[nt][1];
            kv[mt][nt][2] += b2[nt][0];
            kv[mt][nt][3] += b2[nt][1];
        }
}

// RK stage frame: one fused f-eval, apply BODY per fragment element, store next u
#define RK_FRAME(BODY)                                                        \
    {                                                                         \
        float kv[2][4][4];                                                    \
        feval2(sbA, rb, lane, g, q, bw, bias1, bias2, kv);                    \
        _Pragma("unroll")                                                     \
        for (int mt = 0; mt < 2; mt++) {                                      \
            int rA = rb + mt * 16 + g;                                        \
            _Pragma("unroll")                                                 \
            for (int nt = 0; nt < 4; nt++) {                                  \
                float uu[4];                                                  \
                _Pragma("unroll")                                             \
                for (int ii = 0; ii < 4; ii++) {                              \
                    int cg = (mt * 16 + nt * 4 + ii) * 128 + t;               \
                    float k = kv[mt][nt][ii];                                 \
                    float Y = yn[mt][nt][ii];                                 \
                    BODY                                                      \
                    yn[mt][nt][ii] = Y;                                       \
                }                                                             \
                store_pair(sbA, rA, nt * 8 + 2 * q, uu[0], uu[1]);            \
                store_pair(sbA, rA + 8, nt * 8 + 2 * q, uu[2], uu[3]);        \
            }                                                                 \
        }                                                                     \
    }

__global__ __launch_bounds__(128)
void ode_kernel(const float* __restrict__ nodes, const float* __restrict__ gl,
                const float* __restrict__ encNW, const float* __restrict__ encNb,
                const float* __restrict__ encEW, const float* __restrict__ encEb,
                const float* __restrict__ b1g, const float* __restrict__ b2g,
                float* __restrict__ out) {
    extern __shared__ char sm[];
    uint32_t sb = smem_u32(sm);
    uint32_t sbA = sb + SM_A;
    int t = threadIdx.x;
    int w = t >> 5, lane = t & 31;
    int g = lane >> 2, q = lane & 3;
    int rb = w * 32;
    int cbase = blockIdx.x * 128;

    // ---- register-stationary B fragments ----
    uint32_t bw[2][4][4][2];
#pragma unroll
    for (int l = 0; l < 2; l++)
#pragma unroll
        for (int k8 = 0; k8 < 4; k8++)
#pragma unroll
            for (int nt = 0; nt < 4; nt++) {
                int n = nt * 8 + g;
                const unsigned short* src = g_wcat + l * 2048 + n * 64 + k8 * 16 + 2 * q;
                bw[l][k8][nt][0] = *(const uint32_t*)(src);
                bw[l][k8][nt][1] = *(const uint32_t*)(src + 8);
            }
    float bias1[4][2], bias2[4][2], pdec[4][2];
#pragma unroll
    for (int nt = 0; nt < 4; nt++) {
        int c = nt * 8 + 2 * q;
        bias1[nt][0] = __ldg(&b1g[c]);     bias1[nt][1] = __ldg(&b1g[c + 1]);
        bias2[nt][0] = __ldg(&b2g[c]);     bias2[nt][1] = __ldg(&b2g[c + 1]);
        pdec[nt][0]  = __ldg(&g_prep[4 + c]);
        pdec[nt][1]  = __ldg(&g_prep[5 + c]);
    }

    // ---- encoder for this thread's node (row t) ----
    int i0 = cbase + t;
    int i = (i0 < NN) ? i0 : (NN - 1);
    float2 nd = reinterpret_cast<const float2*>(nodes)[i];
    float4 sa = g_agg[i];
    float4 ra = g_agg[NN + i];
    float u0[32];
#pragma unroll
    for (int c = 0; c < 10; c++) {
        float wn0 = __ldg(&encNW[c]), wn1 = __ldg(&encNW[10 + c]), bn = __ldg(&encNb[c]);
        u0[c] = fmaf(nd.x, wn0, fmaf(nd.y, wn1, bn));
        float we0 = __ldg(&encEW[c]), we1 = __ldg(&encEW[10 + c]);
        float we2 = __ldg(&encEW[20 + c]), web = __ldg(&encEb[c]);
        u0[10 + c] = fmaf(sa.x, we0, fmaf(sa.y, we1, fmaf(sa.z, we2, sa.w * web)));
        u0[20 + c] = fmaf(ra.x, we0, fmaf(ra.y, we1, fmaf(ra.z, we2, ra.w * web)));
    }
    u0[30] = gl[0];
    u0[31] = gl[1];

    // write split(u0) to A-tile row t (v4-vectorized)
    {
        uint32_t rbyte = (uint32_t)t * 128u;
#pragma unroll
        for (int gq = 0; gq < 4; gq++) {
            uint32_t hh[4], ll[4];
#pragma unroll
            for (int p = 0; p < 4; p++) {
                float a = u0[gq * 8 + 2 * p], b = u0[gq * 8 + 2 * p + 1];
                uint32_t hp = pkbf(a, b);
                float r0 = a - __uint_as_float(hp << 16);
                float r1 = b - __uint_as_float(hp & 0xFFFF0000u);
                hh[p] = hp;
                ll[p] = pkbf(r0, r1);
            }
            uint32_t ah = sbA + SW128(rbyte + gq * 16);
            asm volatile("st.shared.v4.b32 [%0], {%1,%2,%3,%4};"
                         :: "r"(ah), "r"(hh[0]), "r"(hh[1]), "r"(hh[2]), "r"(hh[3]) : "memory");
            uint32_t al = sbA + SW128(rbyte + 64 + gq * 16);
            asm volatile("st.shared.v4.b32 [%0], {%1,%2,%3,%4};"
                         :: "r"(al), "r"(ll[0]), "r"(ll[1]), "r"(ll[2]), "r"(ll[3]) : "memory");
        }
    }
    // stage u0 (fp32) into K1 region for yn-frag init
    float* scr = (float*)(sm + SM_K1);
#pragma unroll
    for (int c = 0; c < 32; c++) scr[c * 128 + t] = u0[c];
    __syncwarp();

    float yn[2][4][4];
#pragma unroll
    for (int mt = 0; mt < 2; mt++)
#pragma unroll
        for (int nt = 0; nt < 4; nt++)
#pragma unroll
            for (int ii = 0; ii < 4; ii++) {
                int row = rb + mt * 16 + (ii >> 1) * 8 + g;
                int col = nt * 8 + 2 * q + (ii & 1);
                yn[mt][nt][ii] = scr[col * 128 + row];
            }
    __syncwarp();

    float* k1s = (float*)(sm + SM_K1);
    float* k2s = (float*)(sm + SM_K2);
    float* k3s = (float*)(sm + SM_K3);
    float* k4s = (float*)(sm + SM_K4);

#pragma unroll 1
    for (int st = 0; st < 10; ++st) {
        RK_FRAME({ k1s[cg] = k; Y = fmaf(k, C_B1, Y); uu[ii] = fmaf(k, C_R1, Y); })
        RK_FRAME({ k2s[cg] = k; float tv = fmaf(k1s[cg], C_S31, Y); uu[ii] = fmaf(k, C_R2, tv); })
        RK_FRAME({ k3s[cg] = k; Y = fmaf(k, C_B3, Y);
                   float tv = fmaf(k1s[cg], C_S41, Y);
                   tv = fmaf(k2s[cg], C_S42, tv);
                   uu[ii] = fmaf(k, C_R3, tv); })
        RK_FRAME({ k4s[cg] = k; Y = fmaf(k, C_B4, Y);
                   float tv = fmaf(k1s[cg], C_S51, Y);
                   tv = fmaf(k2s[cg], C_S52, tv);
                   tv = fmaf(k3s[cg], C_S53, tv);
                   uu[ii] = fmaf(k, C_R4, tv); })
        RK_FRAME({ Y = fmaf(k, C_B5, Y);
                   float tv = fmaf(k1s[cg], C_S61, Y);
                   tv = fmaf(k2s[cg], C_S62, tv);
                   tv = fmaf(k3s[cg], C_S63, tv);
                   tv = fmaf(k4s[cg], C_S64, tv);
                   uu[ii] = fmaf(k, C_R5, tv); })
        RK_FRAME({ Y = fmaf(k, C_B6, Y); uu[ii] = Y; })
    }

    // ---- decode + integrator epilogue (frag space, shfl row-reduce) ----
    float qc = __ldg(&g_prep[36]);
#pragma unroll
    for (int mt = 0; mt < 2; mt++) {
        float s1 = 0.f, s2 = 0.f;
#pragma unroll
        for (int nt = 0; nt < 4; nt++) {
            s1 = fmaf(yn[mt][nt][0], pdec[nt][0], fmaf(yn[mt][nt][1], pdec[nt][1], s1));
            s2 = fmaf(yn[mt][nt][2], pdec[nt][0], fmaf(yn[mt][nt][3], pdec[nt][1], s2));
        }
        s1 += __shfl_xor_sync(0xFFFFFFFFu, s1, 1);
        s1 += __shfl_xor_sync(0xFFFFFFFFu, s1, 2);
        s2 += __shfl_xor_sync(0xFFFFFFFFu, s2, 1);
        s2 += __shfl_xor_sync(0xFFFFFFFFu, s2, 2);
        if (q == 0) {
            int iA = cbase + rb + mt * 16 + g;
            int iB = iA + 8;
            if (iA < NN) {
                float2 n2 = reinterpret_cast<const float2*>(nodes)[iA];
                float dec = s1 + qc;
                out[iA] = dec;
                float vel = n2.y + dec;
                out[OUT_VEL + iA] = vel;
                out[OUT_POS + iA] = n2.x + vel;
            }
            if (iB < NN) {
                float2 n2 = reinterpret_cast<const float2*>(nodes)[iB];
                float dec = s2 + qc;
                out[iB] = dec;
                float vel = n2.y + dec;
                out[OUT_VEL + iB] = vel;
                out[OUT_POS + iB] = n2.x + vel;
            }
        }
    }
}

extern "C" void kernel_launch(void* const* d_in, const int* in_sizes, int n_in,
                              void* d_out, int out_size) {
    const float* nodes     = (const float*)d_in[0];
    const float* edges     = (const float*)d_in[1];
    const int*   senders   = (const int*)d_in[2];
    const int*   receivers = (const int*)d_in[3];
    const float* globals_  = (const float*)d_in[4];
    const float* encNW     = (const float*)d_in[5];
    const float* encNb     = (const float*)d_in[6];
    const float* encEW     = (const float*)d_in[7];
    const float* encEb     = (const float*)d_in[8];
    const float* odeW1     = (const float*)d_in[9];
    const float* odeb1     = (const float*)d_in[10];
    const float* odeW2     = (const float*)d_in[11];
    const float* odeb2     = (const float*)d_in[12];
    const float* noW       = (const float*)d_in[13];
    const float* nob       = (const float*)d_in[14];
    const float* decNW     = (const float*)d_in[15];
    const float* decNb     = (const float*)d_in[16];
    const float* decEW     = (const float*)d_in[17];
    const float* decEb     = (const float*)d_in[18];
    float* out = (float*)d_out;

    cudaFuncSetAttribute(ode_kernel, cudaFuncAttributeMaxDynamicSharedMemorySize, SM_TOTAL);

    prep_kernel<<<1, 128>>>(encEW, encEb, decEW, decEb, noW, nob, decNW, decNb,
                            odeW1, odeW2);
    zero_kernel<<<(2 * NN + 255) / 256, 256>>>();
    edge_kernel<<<(NE + 255) / 256, 256>>>(edges, senders, receivers, out);
    int nblk = (NN + 127) / 128;
    ode_kernel<<<nblk, 128, SM_TOTAL>>>(nodes, globals_, encNW, encNb, encEW, encEb,
                                        odeb1, odeb2, out);
}

// round 11
// speedup vs baseline: 38.5978x; 1.2220x over previous
#include <cuda_runtime.h>
#include <cuda_bf16.h>
#include <cstdint>

#define NN 100000
#define NE 1600000
#define OUT_DECE (NN)
#define OUT_POS  (NN + NE)
#define OUT_VEL  (NN + NE + NN)

// ---------------- device-global scratch ----------------
__device__ float4 g_agg[2 * NN];
__device__ float  g_prep[40];
// split bf16 weights: [l][n(32)][k(64)]: k<32 = hi(W[k][n]), k>=32 = lo residual
__device__ __align__(16) unsigned short g_wcat[2 * 32 * 64];

// ---------------- RK coefficients (H=0.1 absorbed, rebased on yn) ----------------
#define C_B1   ((float)(0.1 * (35.0/384.0)))
#define C_B3   ((float)(0.1 * (500.0/1113.0)))
#define C_B4   ((float)(0.1 * (125.0/192.0)))
#define C_B5   ((float)(0.1 * (-2187.0/6784.0)))
#define C_B6   ((float)(0.1 * (11.0/84.0)))
#define C_R1   ((float)(0.1 * (1.0/5.0 - 35.0/384.0)))
#define C_S31  ((float)(0.1 * (3.0/40.0 - 35.0/384.0)))
#define C_R2   ((float)(0.1 * (9.0/40.0)))
#define C_S41  ((float)(0.1 * (44.0/45.0 - 35.0/384.0)))
#define C_S42  ((float)(0.1 * (-56.0/15.0)))
#define C_R3   ((float)(0.1 * (32.0/9.0 - 500.0/1113.0)))
#define C_S51  ((float)(0.1 * (19372.0/6561.0 - 35.0/384.0)))
#define C_S52  ((float)(0.1 * (-25360.0/2187.0)))
#define C_S53  ((float)(0.1 * (64448.0/6561.0 - 500.0/1113.0)))
#define C_R4   ((float)(0.1 * (-212.0/729.0 - 125.0/192.0)))
#define C_S61  ((float)(0.1 * (9017.0/3168.0 - 35.0/384.0)))
#define C_S62  ((float)(0.1 * (-355.0/33.0)))
#define C_S63  ((float)(0.1 * (46732.0/5247.0 - 500.0/1113.0)))
#define C_S64  ((float)(0.1 * (49.0/176.0 - 125.0/192.0)))
#define C_R5   ((float)(0.1 * (-5103.0/18656.0 + 2187.0/6784.0)))

// ---------------- helpers ----------------
__device__ __forceinline__ uint32_t smem_u32(const void* p) {
    uint32_t a;
    asm("{ .reg .u64 t; cvta.to.shared.u64 t, %1; cvt.u32.u64 %0, t; }" : "=r"(a) : "l"(p));
    return a;
}
// pack (lo, hi) floats -> bf16x2 (first arg in low 16 bits)
__device__ __forceinline__ uint32_t pkbf(float lo, float hi) {
    uint32_t r;
    asm("cvt.rn.bf16x2.f32 %0, %1, %2;" : "=r"(r) : "f"(hi), "f"(lo));
    return r;
}
__device__ __forceinline__ void mma16816(float d[4], const uint32_t a[4], const uint32_t b[2]) {
    asm volatile("mma.sync.aligned.m16n8k16.row.col.f32.bf16.bf16.f32 "
                 "{%0,%1,%2,%3}, {%4,%5,%6,%7}, {%8,%9}, {%0,%1,%2,%3};"
                 : "+f"(d[0]), "+f"(d[1]), "+f"(d[2]), "+f"(d[3])
                 : "r"(a[0]), "r"(a[1]), "r"(a[2]), "r"(a[3]), "r"(b[0]), "r"(b[1]));
}

// ---------------- precompute kernel ----------------
__global__ void prep_kernel(const float* __restrict__ eW, const float* __restrict__ eb,
                            const float* __restrict__ decEW, const float* __restrict__ decEb,
                            const float* __restrict__ noW, const float* __restrict__ nob,
                            const float* __restrict__ decNW, const float* __restrict__ decNb,
                            const float* __restrict__ odeW1, const float* __restrict__ odeW2) {
    int t = threadIdx.x;   // 128
    if (t < 3) {
        float s = 0.f;
        for (int c = 0; c < 10; c++) s += eW[t * 10 + c] * decEW[c];
        g_prep[t] = s;
    } else if (t == 3) {
        float s = decEb[0];
        for (int c = 0; c < 10; c++) s += eb[c] * decEW[c];
        g_prep[3] = s;
    } else if (t >= 4 && t < 36) {
        int j = t - 4;
        float s = 0.f;
        for (int c = 0; c < 10; c++) s += noW[j * 10 + c] * decNW[c];
        g_prep[t] = s;
    } else if (t == 36) {
        float s = decNb[0];
        for (int c = 0; c < 10; c++) s += nob[c] * decNW[c];
        g_prep[36] = s;
    }
    if (t < 64) {
        int l = t >> 5, n = t & 31;
        const float* W = l ? odeW2 : odeW1;
        unsigned short* dst = &g_wcat[l * 2048 + n * 64];
        for (int kk = 0; kk < 32; kk++) {
            float f = W[kk * 32 + n];
            __nv_bfloat16 hi = __float2bfloat16(f);
            __nv_bfloat16 lo = __float2bfloat16(f - __bfloat162float(hi));
            dst[kk]      = __bfloat16_as_ushort(hi);
            dst[32 + kk] = __bfloat16_as_ushort(lo);
        }
    }
}

__global__ void zero_kernel() {
    int i = blockIdx.x * blockDim.x + threadIdx.x;
    if (i < 2 * NN) g_agg[i] = make_float4(0.f, 0.f, 0.f, 0.f);
}

// ---------------- edge kernel ----------------
__global__ void edge_kernel(const float* __restrict__ edges,
                            const int* __restrict__ senders,
                            const int* __restrict__ receivers,
                            float* __restrict__ out) {
    int e = blockIdx.x * blockDim.x + threadIdx.x;
    if (e >= NE) return;
    float e0 = edges[3 * e + 0];
    float e1 = edges[3 * e + 1];
    float e2 = edges[3 * e + 2];
    int s = senders[e];
    int r = receivers[e];
    float c0 = g_prep[0], c1 = g_prep[1], c2 = g_prep[2], d = g_prep[3];
    out[OUT_DECE + e] = fmaf(e0, c0, fmaf(e1, c1, fmaf(e2, c2, d)));
    float4* ps = &g_agg[s];
    float4* pr = &g_agg[NN + r];
    asm volatile("red.global.add.v4.f32 [%0], {%1, %2, %3, %4};"
                 :: "l"(ps), "f"(e0), "f"(e1), "f"(e2), "f"(1.0f) : "memory");
    asm volatile("red.global.add.v4.f32 [%0], {%1, %2, %3, %4};"
                 :: "l"(pr), "f"(e0), "f"(e1), "f"(e2), "f"(1.0f) : "memory");
}

// ---------------- smem layout: only k1..k4 slots + init scratch ----------------
#define SM_K1   0
#define SM_K2   (SM_K1 + 16384)
#define SM_K3   (SM_K2 + 16384)
#define SM_K4   (SM_K3 + 16384)
#define SM_TOTAL (SM_K4 + 16384)   /* 64 KB */

// Build bf16 hi/lo A-fragments from fp32 value fragments (one 16-row m-tile).
// C-frag (m16n8) -> A-frag (m16n8k16) layout identity:
//   a[j] of k-tile kt:  nt = 2*kt + (j>>1), elements (j&1)*2, (j&1)*2+1
__device__ __forceinline__ void mkfrag(const float (&v)[4][4],
                                       uint32_t (&ah)[2][4], uint32_t (&al)[2][4]) {
#pragma unroll
    for (int kt = 0; kt < 2; kt++)
#pragma unroll
        for (int j = 0; j < 4; j++) {
            int nt = 2 * kt + (j >> 1);
            int b = (j & 1) * 2;
            float x = v[nt][b], y = v[nt][b + 1];
            uint32_t hp = pkbf(x, y);
            float r0 = x - __uint_as_float(hp << 16);
            float r1 = y - __uint_as_float(hp & 0xFFFF0000u);
            ah[kt][j] = hp;
            al[kt][j] = pkbf(r0, r1);
        }
}

// fully register-resident f-eval: kv = f(v). No smem, no syncs, no ldmatrix.
__device__ __forceinline__ void feval_reg(const float (&v)[2][4][4],
                                          const uint32_t (&bw)[2][4][4][2],
                                          const float (&b1)[4][2], const float (&b2)[4][2],
                                          float (&kv)[2][4][4]) {
    uint32_t ah[2][2][4], al[2][2][4];
#pragma unroll
    for (int mt = 0; mt < 2; mt++) mkfrag(v[mt], ah[mt], al[mt]);
    float d[2][4][4];
#pragma unroll
    for (int mt = 0; mt < 2; mt++)
#pragma unroll
        for (int nt = 0; nt < 4; nt++) {
#pragma unroll
            for (int ii = 0; ii < 4; ii++) d[mt][nt][ii] = 0.f;
            mma16816(d[mt][nt], ah[mt][0], bw[0][0][nt]);   // hi * Whi
            mma16816(d[mt][nt], ah[mt][1], bw[0][1][nt]);
            mma16816(d[mt][nt], ah[mt][0], bw[0][2][nt]);   // hi * Wlo
            mma16816(d[mt][nt], ah[mt][1], bw[0][3][nt]);
            mma16816(d[mt][nt], al[mt][0], bw[0][0][nt]);   // lo * Whi
            mma16816(d[mt][nt], al[mt][1], bw[0][1][nt]);
        }
    // h = relu(d + b1), re-fragment in registers
#pragma unroll
    for (int mt = 0; mt < 2; mt++) {
#pragma unroll
        for (int nt = 0; nt < 4; nt++)
#pragma unroll
            for (int ii = 0; ii < 4; ii++)
                d[mt][nt][ii] = fmaxf(d[mt][nt][ii] + b1[nt][ii & 1], 0.f);
        mkfrag(d[mt], ah[mt], al[mt]);
    }
#pragma unroll
    for (int mt = 0; mt < 2; mt++)
#pragma unroll
        for (int nt = 0; nt < 4; nt++) {
#pragma unroll
            for (int ii = 0; ii < 4; ii++) kv[mt][nt][ii] = 0.f;
            mma16816(kv[mt][nt], ah[mt][0], bw[1][0][nt]);
            mma16816(kv[mt][nt], ah[mt][1], bw[1][1][nt]);
            mma16816(kv[mt][nt], ah[mt][0], bw[1][2][nt]);
            mma16816(kv[mt][nt], ah[mt][1], bw[1][3][nt]);
            mma16816(kv[mt][nt], al[mt][0], bw[1][0][nt]);
            mma16816(kv[mt][nt], al[mt][1], bw[1][1][nt]);
#pragma unroll
            for (int ii = 0; ii < 4; ii++) kv[mt][nt][ii] += b2[nt][ii & 1];
        }
}

// RK stage frame: register f-eval + per-element scalar body (uu = next-stage input)
#define RK_FRAME(BODY)                                                        \
    {                                                                         \
        float kv[2][4][4];                                                    \
        feval_reg(v, bw, bias1, bias2, kv);                                   \
        _Pragma("unroll")                                                     \
        for (int mt = 0; mt < 2; mt++)                                        \
        _Pragma("unroll")                                                     \
        for (int nt = 0; nt < 4; nt++)                                        \
        _Pragma("unroll")                                                     \
        for (int ii = 0; ii < 4; ii++) {                                      \
            int cg = (mt * 16 + nt * 4 + ii) * 128 + t;                       \
            float k = kv[mt][nt][ii];                                         \
            float Y = yn[mt][nt][ii];                                         \
            float uu;                                                         \
            BODY                                                              \
            yn[mt][nt][ii] = Y;                                               \
            v[mt][nt][ii] = uu;                                               \
        }                                                                     \
    }

__global__ __launch_bounds__(128)
void ode_kernel(const float* __restrict__ nodes, const float* __restrict__ gl,
                const float* __restrict__ encNW, const float* __restrict__ encNb,
                const float* __restrict__ encEW, const float* __restrict__ encEb,
                const float* __restrict__ b1g, const float* __restrict__ b2g,
                float* __restrict__ out) {
    extern __shared__ char sm[];
    int t = threadIdx.x;
    int w = t >> 5, lane = t & 31;
    int g = lane >> 2, q = lane & 3;
    int rb = w * 32;
    int cbase = blockIdx.x * 128;

    // ---- register-stationary B fragments ----
    uint32_t bw[2][4][4][2];
#pragma unroll
    for (int l = 0; l < 2; l++)
#pragma unroll
        for (int k8 = 0; k8 < 4; k8++)
#pragma unroll
            for (int nt = 0; nt < 4; nt++) {
                int n = nt * 8 + g;
                const unsigned short* src = g_wcat + l * 2048 + n * 64 + k8 * 16 + 2 * q;
                bw[l][k8][nt][0] = *(const uint32_t*)(src);
                bw[l][k8][nt][1] = *(const uint32_t*)(src + 8);
            }
    float bias1[4][2], bias2[4][2], pdec[4][2];
#pragma unroll
    for (int nt = 0; nt < 4; nt++) {
        int c = nt * 8 + 2 * q;
        bias1[nt][0] = __ldg(&b1g[c]);     bias1[nt][1] = __ldg(&b1g[c + 1]);
        bias2[nt][0] = __ldg(&b2g[c]);     bias2[nt][1] = __ldg(&b2g[c + 1]);
        pdec[nt][0]  = __ldg(&g_prep[4 + c]);
        pdec[nt][1]  = __ldg(&g_prep[5 + c]);
    }

    // ---- encoder for this thread's node (row t) ----
    int i0 = cbase + t;
    int i = (i0 < NN) ? i0 : (NN - 1);
    float2 nd = reinterpret_cast<const float2*>(nodes)[i];
    float4 sa = g_agg[i];
    float4 ra = g_agg[NN + i];
    float u0[32];
#pragma unroll
    for (int c = 0; c < 10; c++) {
        float wn0 = __ldg(&encNW[c]), wn1 = __ldg(&encNW[10 + c]), bn = __ldg(&encNb[c]);
        u0[c] = fmaf(nd.x, wn0, fmaf(nd.y, wn1, bn));
        float we0 = __ldg(&encEW[c]), we1 = __ldg(&encEW[10 + c]);
        float we2 = __ldg(&encEW[20 + c]), web = __ldg(&encEb[c]);
        u0[10 + c] = fmaf(sa.x, we0, fmaf(sa.y, we1, fmaf(sa.z, we2, sa.w * web)));
        u0[20 + c] = fmaf(ra.x, we0, fmaf(ra.y, we1, fmaf(ra.z, we2, ra.w * web)));
    }
    u0[30] = gl[0];
    u0[31] = gl[1];

    // stage u0 into smem scratch, gather fragments (warp-local rows only)
    float* scr = (float*)(sm + SM_K1);
#pragma unroll
    for (int c = 0; c < 32; c++) scr[c * 128 + t] = u0[c];
    __syncwarp();

    float yn[2][4][4], v[2][4][4];
#pragma unroll
    for (int mt = 0; mt < 2; mt++)
#pragma unroll
        for (int nt = 0; nt < 4; nt++)
#pragma unroll
            for (int ii = 0; ii < 4; ii++) {
                int row = rb + mt * 16 + (ii >> 1) * 8 + g;
                int col = nt * 8 + 2 * q + (ii & 1);
                float val = scr[col * 128 + row];
                yn[mt][nt][ii] = val;
                v[mt][nt][ii] = val;
            }
    __syncwarp();

    float* k1s = (float*)(sm + SM_K1);
    float* k2s = (float*)(sm + SM_K2);
    float* k3s = (float*)(sm + SM_K3);
    float* k4s = (float*)(sm + SM_K4);

#pragma unroll 1
    for (int st = 0; st < 10; ++st) {
        RK_FRAME({ k1s[cg] = k; Y = fmaf(k, C_B1, Y); uu = fmaf(k, C_R1, Y); })
        RK_FRAME({ k2s[cg] = k; float tv = fmaf(k1s[cg], C_S31, Y); uu = fmaf(k, C_R2, tv); })
        RK_FRAME({ k3s[cg] = k; Y = fmaf(k, C_B3, Y);
                   float tv = fmaf(k1s[cg], C_S41, Y);
                   tv = fmaf(k2s[cg], C_S42, tv);
                   uu = fmaf(k, C_R3, tv); })
        RK_FRAME({ k4s[cg] = k; Y = fmaf(k, C_B4, Y);
                   float tv = fmaf(k1s[cg], C_S51, Y);
                   tv = fmaf(k2s[cg], C_S52, tv);
                   tv = fmaf(k3s[cg], C_S53, tv);
                   uu = fmaf(k, C_R4, tv); })
        RK_FRAME({ Y = fmaf(k, C_B5, Y);
                   float tv = fmaf(k1s[cg], C_S61, Y);
                   tv = fmaf(k2s[cg], C_S62, tv);
                   tv = fmaf(k3s[cg], C_S63, tv);
                   tv = fmaf(k4s[cg], C_S64, tv);
                   uu = fmaf(k, C_R5, tv); })
        RK_FRAME({ Y = fmaf(k, C_B6, Y); uu = Y; })
    }

    // ---- decode + integrator epilogue (frag space, shfl row-reduce) ----
    float qc = __ldg(&g_prep[36]);
#pragma unroll
    for (int mt = 0; mt < 2; mt++) {
        float s1 = 0.f, s2 = 0.f;
#pragma unroll
        for (int nt = 0; nt < 4; nt++) {
            s1 = fmaf(yn[mt][nt][0], pdec[nt][0], fmaf(yn[mt][nt][1], pdec[nt][1], s1));
            s2 = fmaf(yn[mt][nt][2], pdec[nt][0], fmaf(yn[mt][nt][3], pdec[nt][1], s2));
        }
        s1 += __shfl_xor_sync(0xFFFFFFFFu, s1, 1);
        s1 += __shfl_xor_sync(0xFFFFFFFFu, s1, 2);
        s2 += __shfl_xor_sync(0xFFFFFFFFu, s2, 1);
        s2 += __shfl_xor_sync(0xFFFFFFFFu, s2, 2);
        if (q == 0) {
            int iA = cbase + rb + mt * 16 + g;
            int iB = iA + 8;
            if (iA < NN) {
                float2 n2 = reinterpret_cast<const float2*>(nodes)[iA];
                float dec = s1 + qc;
                out[iA] = dec;
                float vel = n2.y + dec;
                out[OUT_VEL + iA] = vel;
                out[OUT_POS + iA] = n2.x + vel;
            }
            if (iB < NN) {
                float2 n2 = reinterpret_cast<const float2*>(nodes)[iB];
                float dec = s2 + qc;
                out[iB] = dec;
                float vel = n2.y + dec;
                out[OUT_VEL + iB] = vel;
                out[OUT_POS + iB] = n2.x + vel;
            }
        }
    }
}

extern "C" void kernel_launch(void* const* d_in, const int* in_sizes, int n_in,
                              void* d_out, int out_size) {
    const float* nodes     = (const float*)d_in[0];
    const float* edges     = (const float*)d_in[1];
    const int*   senders   = (const int*)d_in[2];
    const int*   receivers = (const int*)d_in[3];
    const float* globals_  = (const float*)d_in[4];
    const float* encNW     = (const float*)d_in[5];
    const float* encNb     = (const float*)d_in[6];
    const float* encEW     = (const float*)d_in[7];
    const float* encEb     = (const float*)d_in[8];
    const float* odeW1     = (const float*)d_in[9];
    const float* odeb1     = (const float*)d_in[10];
    const float* odeW2     = (const float*)d_in[11];
    const float* odeb2     = (const float*)d_in[12];
    const float* noW       = (const float*)d_in[13];
    const float* nob       = (const float*)d_in[14];
    const float* decNW     = (const float*)d_in[15];
    const float* decNb     = (const float*)d_in[16];
    const float* decEW     = (const float*)d_in[17];
    const float* decEb     = (const float*)d_in[18];
    float* out = (float*)d_out;

    cudaFuncSetAttribute(ode_kernel, cudaFuncAttributeMaxDynamicSharedMemorySize, SM_TOTAL);

    prep_kernel<<<1, 128>>>(encEW, encEb, decEW, decEb, noW, nob, decNW, decNb,
                            odeW1, odeW2);
    zero_kernel<<<(2 * NN + 255) / 256, 256>>>();
    edge_kernel<<<(NE + 255) / 256, 256>>>(edges, senders, receivers, out);
    int nblk = (NN + 127) / 128;
    ode_kernel<<<nblk, 128, SM_TOTAL>>>(nodes, globals_, encNW, encNb, encEW, encEb,
                                        odeb1, odeb2, out);
}

// round 12
// speedup vs baseline: 44.1388x; 1.1436x over previous
#include <cuda_runtime.h>
#include <cuda_bf16.h>
#include <cstdint>

#define NN 100000
#define NE 1600000
#define OUT_DECE (NN)
#define OUT_POS  (NN + NE)
#define OUT_VEL  (NN + NE + NN)

// ---------------- device-global scratch ----------------
__device__ float4 g_agg[2 * NN];
__device__ float  g_prep[40];
// split bf16 weights: [l][n(32)][k(64)]: k<32 = hi(W[k][n]), k>=32 = lo residual
__device__ __align__(16) unsigned short g_wcat[2 * 32 * 64];

// ---------------- RK coefficients (H=0.1 absorbed, rebased on yn) ----------------
#define C_B1   ((float)(0.1 * (35.0/384.0)))
#define C_B3   ((float)(0.1 * (500.0/1113.0)))
#define C_B4   ((float)(0.1 * (125.0/192.0)))
#define C_B5   ((float)(0.1 * (-2187.0/6784.0)))
#define C_B6   ((float)(0.1 * (11.0/84.0)))
#define C_R1   ((float)(0.1 * (1.0/5.0 - 35.0/384.0)))
#define C_S31  ((float)(0.1 * (3.0/40.0 - 35.0/384.0)))
#define C_R2   ((float)(0.1 * (9.0/40.0)))
#define C_S41  ((float)(0.1 * (44.0/45.0 - 35.0/384.0)))
#define C_S42  ((float)(0.1 * (-56.0/15.0)))
#define C_R3   ((float)(0.1 * (32.0/9.0 - 500.0/1113.0)))
#define C_S51  ((float)(0.1 * (19372.0/6561.0 - 35.0/384.0)))
#define C_S52  ((float)(0.1 * (-25360.0/2187.0)))
#define C_S53  ((float)(0.1 * (64448.0/6561.0 - 500.0/1113.0)))
#define C_R4   ((float)(0.1 * (-212.0/729.0 - 125.0/192.0)))
#define C_S61  ((float)(0.1 * (9017.0/3168.0 - 35.0/384.0)))
#define C_S62  ((float)(0.1 * (-355.0/33.0)))
#define C_S63  ((float)(0.1 * (46732.0/5247.0 - 500.0/1113.0)))
#define C_S64  ((float)(0.1 * (49.0/176.0 - 125.0/192.0)))
#define C_R5   ((float)(0.1 * (-5103.0/18656.0 + 2187.0/6784.0)))

// ---------------- helpers ----------------
// pack (lo, hi) floats -> bf16x2 (first arg in low 16 bits)
__device__ __forceinline__ uint32_t pkbf(float lo, float hi) {
    uint32_t r;
    asm("cvt.rn.bf16x2.f32 %0, %1, %2;" : "=r"(r) : "f"(hi), "f"(lo));
    return r;
}
__device__ __forceinline__ void mma16816(float d[4], const uint32_t a[4], const uint32_t b[2]) {
    asm volatile("mma.sync.aligned.m16n8k16.row.col.f32.bf16.bf16.f32 "
                 "{%0,%1,%2,%3}, {%4,%5,%6,%7}, {%8,%9}, {%0,%1,%2,%3};"
                 : "+f"(d[0]), "+f"(d[1]), "+f"(d[2]), "+f"(d[3])
                 : "r"(a[0]), "r"(a[1]), "r"(a[2]), "r"(a[3]), "r"(b[0]), "r"(b[1]));
}

// ---------------- precompute kernel ----------------
__global__ void prep_kernel(const float* __restrict__ eW, const float* __restrict__ eb,
                            const float* __restrict__ decEW, const float* __restrict__ decEb,
                            const float* __restrict__ noW, const float* __restrict__ nob,
                            const float* __restrict__ decNW, const float* __restrict__ decNb,
                            const float* __restrict__ odeW1, const float* __restrict__ odeW2) {
    int t = threadIdx.x;   // 128
    if (t < 3) {
        float s = 0.f;
        for (int c = 0; c < 10; c++) s += eW[t * 10 + c] * decEW[c];
        g_prep[t] = s;
    } else if (t == 3) {
        float s = decEb[0];
        for (int c = 0; c < 10; c++) s += eb[c] * decEW[c];
        g_prep[3] = s;
    } else if (t >= 4 && t < 36) {
        int j = t - 4;
        float s = 0.f;
        for (int c = 0; c < 10; c++) s += noW[j * 10 + c] * decNW[c];
        g_prep[t] = s;
    } else if (t == 36) {
        float s = decNb[0];
        for (int c = 0; c < 10; c++) s += nob[c] * decNW[c];
        g_prep[36] = s;
    }
    if (t < 64) {
        int l = t >> 5, n = t & 31;
        const float* W = l ? odeW2 : odeW1;
        unsigned short* dst = &g_wcat[l * 2048 + n * 64];
        for (int kk = 0; kk < 32; kk++) {
            float f = W[kk * 32 + n];
            __nv_bfloat16 hi = __float2bfloat16(f);
            __nv_bfloat16 lo = __float2bfloat16(f - __bfloat162float(hi));
            dst[kk]      = __bfloat16_as_ushort(hi);
            dst[32 + kk] = __bfloat16_as_ushort(lo);
        }
    }
}

__global__ void zero_kernel() {
    int i = blockIdx.x * blockDim.x + threadIdx.x;
    if (i < 2 * NN) g_agg[i] = make_float4(0.f, 0.f, 0.f, 0.f);
}

// ---------------- edge kernel ----------------
__global__ void edge_kernel(const float* __restrict__ edges,
                            const int* __restrict__ senders,
                            const int* __restrict__ receivers,
                            float* __restrict__ out) {
    int e = blockIdx.x * blockDim.x + threadIdx.x;
    if (e >= NE) return;
    float e0 = edges[3 * e + 0];
    float e1 = edges[3 * e + 1];
    float e2 = edges[3 * e + 2];
    int s = senders[e];
    int r = receivers[e];
    float c0 = g_prep[0], c1 = g_prep[1], c2 = g_prep[2], d = g_prep[3];
    out[OUT_DECE + e] = fmaf(e0, c0, fmaf(e1, c1, fmaf(e2, c2, d)));
    float4* ps = &g_agg[s];
    float4* pr = &g_agg[NN + r];
    asm volatile("red.global.add.v4.f32 [%0], {%1, %2, %3, %4};"
                 :: "l"(ps), "f"(e0), "f"(e1), "f"(e2), "f"(1.0f) : "memory");
    asm volatile("red.global.add.v4.f32 [%0], {%1, %2, %3, %4};"
                 :: "l"(pr), "f"(e0), "f"(e1), "f"(e2), "f"(1.0f) : "memory");
}

// ---------------- smem: k1..k4 thread-private slots (+init scratch overlay) ----
#define SM_K1   0
#define SM_K2   (SM_K1 + 8192)
#define SM_K3   (SM_K2 + 8192)
#define SM_K4   (SM_K3 + 8192)
#define SM_TOTAL (SM_K4 + 8192)   /* 32 KB */

// Build bf16 hi/lo A-fragments from fp32 value fragments (one 16-row m-tile).
// C-frag (m16n8) -> A-frag (m16n8k16) layout identity:
//   a[j] of k-tile kt:  nt = 2*kt + (j>>1), elements (j&1)*2, (j&1)*2+1
__device__ __forceinline__ void mkfrag(const float (&v)[4][4],
                                       uint32_t (&ah)[2][4], uint32_t (&al)[2][4]) {
#pragma unroll
    for (int kt = 0; kt < 2; kt++)
#pragma unroll
        for (int j = 0; j < 4; j++) {
            int nt = 2 * kt + (j >> 1);
            int b = (j & 1) * 2;
            float x = v[nt][b], y = v[nt][b + 1];
            uint32_t hp = pkbf(x, y);
            float r0 = x - __uint_as_float(hp << 16);
            float r1 = y - __uint_as_float(hp & 0xFFFF0000u);
            ah[kt][j] = hp;
            al[kt][j] = pkbf(r0, r1);
        }
}

// fully register-resident f-eval, one m16-tile: kv = f(v).
__device__ __forceinline__ void feval_reg(const float (&v)[4][4],
                                          const uint32_t (&bw)[2][4][4][2],
                                          const float (&b1)[4][2], const float (&b2)[4][2],
                                          float (&kv)[4][4]) {
    uint32_t ah[2][4], al[2][4];
    mkfrag(v, ah, al);
    float d[4][4];
#pragma unroll
    for (int nt = 0; nt < 4; nt++) {
        d[nt][0] = b1[nt][0]; d[nt][1] = b1[nt][1];
        d[nt][2] = b1[nt][0]; d[nt][3] = b1[nt][1];
        mma16816(d[nt], ah[0], bw[0][0][nt]);   // hi * Whi
        mma16816(d[nt], ah[1], bw[0][1][nt]);
        mma16816(d[nt], ah[0], bw[0][2][nt]);   // hi * Wlo
        mma16816(d[nt], ah[1], bw[0][3][nt]);
        mma16816(d[nt], al[0], bw[0][0][nt]);   // lo * Whi
        mma16816(d[nt], al[1], bw[0][1][nt]);
    }
#pragma unroll
    for (int nt = 0; nt < 4; nt++)
#pragma unroll
        for (int ii = 0; ii < 4; ii++) d[nt][ii] = fmaxf(d[nt][ii], 0.f);
    mkfrag(d, ah, al);
#pragma unroll
    for (int nt = 0; nt < 4; nt++) {
        kv[nt][0] = b2[nt][0]; kv[nt][1] = b2[nt][1];
        kv[nt][2] = b2[nt][0]; kv[nt][3] = b2[nt][1];
        mma16816(kv[nt], ah[0], bw[1][0][nt]);
        mma16816(kv[nt], ah[1], bw[1][1][nt]);
        mma16816(kv[nt], ah[0], bw[1][2][nt]);
        mma16816(kv[nt], ah[1], bw[1][3][nt]);
        mma16816(kv[nt], al[0], bw[1][0][nt]);
        mma16816(kv[nt], al[1], bw[1][1][nt]);
    }
}

// RK stage frame
#define RK_FRAME(BODY)                                                        \
    {                                                                         \
        float kv[4][4];                                                       \
        feval_reg(v, bw, bias1, bias2, kv);                                   \
        _Pragma("unroll")                                                     \
        for (int nt = 0; nt < 4; nt++)                                        \
        _Pragma("unroll")                                                     \
        for (int ii = 0; ii < 4; ii++) {                                      \
            int cg = (nt * 4 + ii) * 128 + t;                                 \
            float k = kv[nt][ii];                                             \
            float Y = yn[nt][ii];                                             \
            float uu;                                                         \
            BODY                                                              \
            yn[nt][ii] = Y;                                                   \
            v[nt][ii] = uu;                                                   \
        }                                                                     \
    }

__global__ __launch_bounds__(128)
void ode_kernel(const float* __restrict__ nodes, const float* __restrict__ gl,
                const float* __restrict__ encNW, const float* __restrict__ encNb,
                const float* __restrict__ encEW, const float* __restrict__ encEb,
                const float* __restrict__ b1g, const float* __restrict__ b2g,
                float* __restrict__ out) {
    extern __shared__ char sm[];
    int t = threadIdx.x;
    int w = t >> 5, lane = t & 31;
    int g = lane >> 2, q = lane & 3;
    int rb = w * 16;                    // warp owns 16 local rows
    int cbase = blockIdx.x * 64;        // CTA owns 64 nodes

    // ---- register-stationary B fragments ----
    uint32_t bw[2][4][4][2];
#pragma unroll
    for (int l = 0; l < 2; l++)
#pragma unroll
        for (int k8 = 0; k8 < 4; k8++)
#pragma unroll
            for (int nt = 0; nt < 4; nt++) {
                int n = nt * 8 + g;
                const unsigned short* src = g_wcat + l * 2048 + n * 64 + k8 * 16 + 2 * q;
                bw[l][k8][nt][0] = *(const uint32_t*)(src);
                bw[l][k8][nt][1] = *(const uint32_t*)(src + 8);
            }
    float bias1[4][2], bias2[4][2];
#pragma unroll
    for (int nt = 0; nt < 4; nt++) {
        int c = nt * 8 + 2 * q;
        bias1[nt][0] = __ldg(&b1g[c]);  bias1[nt][1] = __ldg(&b1g[c + 1]);
        bias2[nt][0] = __ldg(&b2g[c]);  bias2[nt][1] = __ldg(&b2g[c + 1]);
    }

    // ---- encoder: threads 0..63 handle one node each ----
    float* scr = (float*)(sm + SM_K1);   // overlay: [col(32)][node(64)]
    if (t < 64) {
        int i0 = cbase + t;
        int i = (i0 < NN) ? i0 : (NN - 1);
        float2 nd = reinterpret_cast<const float2*>(nodes)[i];
        float4 sa = g_agg[i];
        float4 ra = g_agg[NN + i];
        float u0[32];
#pragma unroll
        for (int c = 0; c < 10; c++) {
            float wn0 = __ldg(&encNW[c]), wn1 = __ldg(&encNW[10 + c]), bn = __ldg(&encNb[c]);
            u0[c] = fmaf(nd.x, wn0, fmaf(nd.y, wn1, bn));
            float we0 = __ldg(&encEW[c]), we1 = __ldg(&encEW[10 + c]);
            float we2 = __ldg(&encEW[20 + c]), web = __ldg(&encEb[c]);
            u0[10 + c] = fmaf(sa.x, we0, fmaf(sa.y, we1, fmaf(sa.z, we2, sa.w * web)));
            u0[20 + c] = fmaf(ra.x, we0, fmaf(ra.y, we1, fmaf(ra.z, we2, ra.w * web)));
        }
        u0[30] = gl[0];
        u0[31] = gl[1];
#pragma unroll
        for (int c = 0; c < 32; c++) scr[c * 64 + t] = u0[c];
    }
    __syncthreads();

    float yn[4][4], v[4][4];
#pragma unroll
    for (int nt = 0; nt < 4; nt++)
#pragma unroll
        for (int ii = 0; ii < 4; ii++) {
            int row = rb + (ii >> 1) * 8 + g;           // local node 0..63
            int col = nt * 8 + 2 * q + (ii & 1);
            float val = scr[col * 64 + row];
            yn[nt][ii] = val;
            v[nt][ii] = val;
        }
    __syncthreads();

    float* k1s = (float*)(sm + SM_K1);
    float* k2s = (float*)(sm + SM_K2);
    float* k3s = (float*)(sm + SM_K3);
    float* k4s = (float*)(sm + SM_K4);

#pragma unroll 1
    for (int st = 0; st < 10; ++st) {
        RK_FRAME({ k1s[cg] = k; Y = fmaf(k, C_B1, Y); uu = fmaf(k, C_R1, Y); })
        RK_FRAME({ k2s[cg] = k; float tv = fmaf(k1s[cg], C_S31, Y); uu = fmaf(k, C_R2, tv); })
        RK_FRAME({ k3s[cg] = k; Y = fmaf(k, C_B3, Y);
                   float tv = fmaf(k1s[cg], C_S41, Y);
                   tv = fmaf(k2s[cg], C_S42, tv);
                   uu = fmaf(k, C_R3, tv); })
        RK_FRAME({ k4s[cg] = k; Y = fmaf(k, C_B4, Y);
                   float tv = fmaf(k1s[cg], C_S51, Y);
                   tv = fmaf(k2s[cg], C_S52, tv);
                   tv = fmaf(k3s[cg], C_S53, tv);
                   uu = fmaf(k, C_R4, tv); })
        RK_FRAME({ Y = fmaf(k, C_B5, Y);
                   float tv = fmaf(k1s[cg], C_S61, Y);
                   tv = fmaf(k2s[cg], C_S62, tv);
                   tv = fmaf(k3s[cg], C_S63, tv);
                   tv = fmaf(k4s[cg], C_S64, tv);
                   uu = fmaf(k, C_R5, tv); })
        RK_FRAME({ Y = fmaf(k, C_B6, Y); uu = Y; })
    }

    // ---- decode + integrator epilogue (frag space, shfl row-reduce) ----
    float qc = __ldg(&g_prep[36]);
    float pdec[4][2];
#pragma unroll
    for (int nt = 0; nt < 4; nt++) {
        int c = nt * 8 + 2 * q;
        pdec[nt][0] = __ldg(&g_prep[4 + c]);
        pdec[nt][1] = __ldg(&g_prep[5 + c]);
    }
    float s1 = 0.f, s2 = 0.f;
#pragma unroll
    for (int nt = 0; nt < 4; nt++) {
        s1 = fmaf(yn[nt][0], pdec[nt][0], fmaf(yn[nt][1], pdec[nt][1], s1));
        s2 = fmaf(yn[nt][2], pdec[nt][0], fmaf(yn[nt][3], pdec[nt][1], s2));
    }
    s1 += __shfl_xor_sync(0xFFFFFFFFu, s1, 1);
    s1 += __shfl_xor_sync(0xFFFFFFFFu, s1, 2);
    s2 += __shfl_xor_sync(0xFFFFFFFFu, s2, 1);
    s2 += __shfl_xor_sync(0xFFFFFFFFu, s2, 2);
    if (q == 0) {
        int iA = cbase + rb + g;
        int iB = iA + 8;
        if (iA < NN) {
            float2 n2 = reinterpret_cast<const float2*>(nodes)[iA];
            float dec = s1 + qc;
            out[iA] = dec;
            float vel = n2.y + dec;
            out[OUT_VEL + iA] = vel;
            out[OUT_POS + iA] = n2.x + vel;
        }
        if (iB < NN) {
            float2 n2 = reinterpret_cast<const float2*>(nodes)[iB];
            float dec = s2 + qc;
            out[iB] = dec;
            float vel = n2.y + dec;
            out[OUT_VEL + iB] = vel;
            out[OUT_POS + iB] = n2.x + vel;
        }
    }
}

extern "C" void kernel_launch(void* const* d_in, const int* in_sizes, int n_in,
                              void* d_out, int out_size) {
    const float* nodes     = (const float*)d_in[0];
    const float* edges     = (const float*)d_in[1];
    const int*   senders   = (const int*)d_in[2];
    const int*   receivers = (const int*)d_in[3];
    const float* globals_  = (const float*)d_in[4];
    const float* encNW     = (const float*)d_in[5];
    const float* encNb     = (const float*)d_in[6];
    const float* encEW     = (const float*)d_in[7];
    const float* encEb     = (const float*)d_in[8];
    const float* odeW1     = (const float*)d_in[9];
    const float* odeb1     = (const float*)d_in[10];
    const float* odeW2     = (const float*)d_in[11];
    const float* odeb2     = (const float*)d_in[12];
    const float* noW       = (const float*)d_in[13];
    const float* nob       = (const float*)d_in[14];
    const float* decNW     = (const float*)d_in[15];
    const float* decNb     = (const float*)d_in[16];
    const float* decEW     = (const float*)d_in[17];
    const float* decEb     = (const float*)d_in[18];
    float* out = (float*)d_out;

    cudaFuncSetAttribute(ode_kernel, cudaFuncAttributeMaxDynamicSharedMemorySize, SM_TOTAL);

    prep_kernel<<<1, 128>>>(encEW, encEb, decEW, decEb, noW, nob, decNW, decNb,
                            odeW1, odeW2);
    zero_kernel<<<(2 * NN + 255) / 256, 256>>>();
    edge_kernel<<<(NE + 255) / 256, 256>>>(edges, senders, receivers, out);
    int nblk = (NN + 63) / 64;
    ode_kernel<<<nblk, 128, SM_TOTAL>>>(nodes, globals_, encNW, encNb, encEW, encEb,
                                        odeb1, odeb2, out);
}